// round 1
// baseline (speedup 1.0000x reference)
#include <cuda_runtime.h>
#include <math.h>

#define H   768
#define NH  12
#define DH  64
#define FF  3072
#define BB  8
#define SEQ 1024
#define ROWS (BB*SEQ)                 // 8192
#define X_ELEMS ((size_t)ROWS*H)      // 6291456
#define W_ELEMS ((size_t)BB*NH*SEQ*SEQ)

// ---------------- scratch (static device allocations; no cudaMalloc) ------
__device__ float g_x1[ROWS*H];
__device__ float g_q [ROWS*H];
__device__ float g_k [ROWS*H];
__device__ float g_v [ROWS*H];
__device__ float g_ctx[ROWS*H];
__device__ float g_xres[ROWS*H];
__device__ float g_x2[ROWS*H];
__device__ float g_h [ROWS*FF];

// ---------------- fast exp (FMA pipe, avoids MUFU throughput wall) --------
__device__ __forceinline__ float fexp(float x) {
    x = fmaxf(x, -87.0f);
    float t  = x * 1.4426950408889634f;
    float fi = rintf(t);
    float z  = t - fi;
    float p  =            1.535336188319500e-4f;
    p = fmaf(p, z, 1.339887440266574e-3f);
    p = fmaf(p, z, 9.618437357674640e-3f);
    p = fmaf(p, z, 5.550332471162809e-2f);
    p = fmaf(p, z, 2.402264791363012e-1f);
    p = fmaf(p, z, 6.931472028550421e-1f);
    p = fmaf(p, z, 1.0f);
    return __int_as_float(((int)fi + 127) << 23) * p;
}

// ---------------- block reduce helper --------------------------------------
__device__ __forceinline__ float block_sum(float v, float* red) {
    #pragma unroll
    for (int o = 16; o; o >>= 1) v += __shfl_xor_sync(0xffffffffu, v, o);
    int w = threadIdx.x >> 5;
    if ((threadIdx.x & 31) == 0) red[w] = v;
    __syncthreads();
    float t = 0.0f;
    if (threadIdx.x < 32) {
        t = (threadIdx.x < 8) ? red[threadIdx.x] : 0.0f;
        #pragma unroll
        for (int o = 4; o; o >>= 1) t += __shfl_xor_sync(0xffffffffu, t, o);
        if (threadIdx.x == 0) red[0] = t;
    }
    __syncthreads();
    t = red[0];
    __syncthreads();
    return t;
}

// ---------------- layernorm: one block per row (H=768 = 256*3) ------------
__global__ __launch_bounds__(256) void ln_kernel(
    const float* __restrict__ x, const float* __restrict__ g,
    const float* __restrict__ b, float* __restrict__ y)
{
    __shared__ float red[8];
    int row = blockIdx.x;
    const float* xr = x + (size_t)row * H;
    int t = threadIdx.x;
    float v0 = xr[t], v1 = xr[t + 256], v2 = xr[t + 512];
    float mu = block_sum(v0 + v1 + v2, red) * (1.0f / H);
    float d0 = v0 - mu, d1 = v1 - mu, d2 = v2 - mu;
    float var = block_sum(d0*d0 + d1*d1 + d2*d2, red) * (1.0f / H);
    float rs = rsqrtf(var + 1e-6f);
    float* yr = y + (size_t)row * H;
    yr[t]       = d0 * rs * g[t]       + b[t];
    yr[t + 256] = d1 * rs * g[t + 256] + b[t + 256];
    yr[t + 512] = d2 * rs * g[t + 512] + b[t + 512];
}

// ---------------- SGEMM: C[M,N] = A[M,K] @ W[K,N] + bias (+gelu) (+res) ---
// 128x128 tile, BK=8, 256 threads, 8x8 per-thread microtile.
// All dims are multiples of tile sizes for this problem (no bounds checks).
template<int ACT>
__global__ __launch_bounds__(256) void gemm_kernel(
    const float* __restrict__ A, const float* __restrict__ W,
    const float* __restrict__ bias, const float* __restrict__ res,
    float* __restrict__ C, int M, int N, int K)
{
    __shared__ float As[8][128];
    __shared__ float Bs[8][128];
    const int tid = threadIdx.x;
    const int m0 = blockIdx.y * 128, n0 = blockIdx.x * 128;
    const int tr = tid >> 4, tc = tid & 15;   // 16x16 thread grid

    const int aRow = tid >> 1;
    const int aCol = (tid & 1) * 4;
    const int bRow = tid >> 5;
    const int bCol = (tid & 31) * 4;

    const float* Ap = A + (size_t)(m0 + aRow) * K + aCol;
    const float* Wp = W + (size_t)bRow * N + n0 + bCol;

    float acc[8][8];
    #pragma unroll
    for (int i = 0; i < 8; i++)
        #pragma unroll
        for (int j = 0; j < 8; j++) acc[i][j] = 0.0f;

    for (int k0 = 0; k0 < K; k0 += 8) {
        float4 av = *(const float4*)(Ap + k0);
        As[aCol + 0][aRow] = av.x;
        As[aCol + 1][aRow] = av.y;
        As[aCol + 2][aRow] = av.z;
        As[aCol + 3][aRow] = av.w;
        *(float4*)&Bs[bRow][bCol] = *(const float4*)(Wp + (size_t)k0 * N);
        __syncthreads();
        #pragma unroll
        for (int kk = 0; kk < 8; kk++) {
            float ra[8], rb[8];
            *(float4*)(ra)     = *(const float4*)&As[kk][tr * 8];
            *(float4*)(ra + 4) = *(const float4*)&As[kk][tr * 8 + 4];
            *(float4*)(rb)     = *(const float4*)&Bs[kk][tc * 8];
            *(float4*)(rb + 4) = *(const float4*)&Bs[kk][tc * 8 + 4];
            #pragma unroll
            for (int i = 0; i < 8; i++)
                #pragma unroll
                for (int j = 0; j < 8; j++)
                    acc[i][j] = fmaf(ra[i], rb[j], acc[i][j]);
        }
        __syncthreads();
    }

    #pragma unroll
    for (int i = 0; i < 8; i++) {
        int row = m0 + tr * 8 + i;
        size_t base = (size_t)row * N + n0 + tc * 8;
        #pragma unroll
        for (int j = 0; j < 8; j++) {
            float c = acc[i][j] + bias[n0 + tc * 8 + j];
            if (ACT == 1) c = 0.5f * c * (1.0f + erff(c * 0.70710678118654752f));
            if (res) c += res[base + j];
            C[base + j] = c;
        }
    }
}

// ---------------- fused attention -----------------------------------------
// Block = (b, h, 32-row q tile). Computes S = Q K^T / sqrt(H) into SMEM,
// softmax in place, writes weights once to gmem, then ctx = P @ V.
#define QT 32
#define SQ_LD 68
#define SKT_LD 132
#define SV_LD 68
#define SS_LD 1028
#define ATT_SMEM ((QT*SQ_LD + DH*SKT_LD + 128*SV_LD + QT*SS_LD) * 4)

__global__ __launch_bounds__(256) void attn_kernel(
    const float* __restrict__ Q, const float* __restrict__ K,
    const float* __restrict__ V, float* __restrict__ Wout,
    float* __restrict__ Ctx)
{
    extern __shared__ float sm[];
    float* sQ  = sm;                       // [32][68]
    float* sKT = sQ  + QT * SQ_LD;         // [64][132]  (K transposed: [k][j])
    float* sV  = sKT + DH * SKT_LD;        // [128][68]
    float* sS  = sV  + 128 * SV_LD;        // [32][1028]

    const int tid = threadIdx.x;
    const int q0 = blockIdx.x * QT;
    const int h  = blockIdx.y;
    const int b  = blockIdx.z;
    const float scale = 0.03608439182435161f;  // 1/sqrt(768)

    const size_t head = (size_t)b * SEQ * H + (size_t)h * DH;
    const float* Qp = Q + head;
    const float* Kp = K + head;
    const float* Vp = V + head;

    // load Q tile [32][64]
    for (int s = tid; s < QT * 16; s += 256) {
        int r = s >> 4, c4 = (s & 15) * 4;
        *(float4*)&sQ[r * SQ_LD + c4] =
            *(const float4*)(Qp + (size_t)(q0 + r) * H + c4);
    }

    const int tr = tid >> 5;   // 0..7
    const int tc = tid & 31;   // 0..31

    // ---- phase 1: scores ----
    for (int jt = 0; jt < 8; jt++) {
        const int j0 = jt * 128;
        __syncthreads();
        // load K tile transposed: sKT[k][j]
        for (int s = tid; s < 128 * 16; s += 256) {
            int j = s >> 4, c4 = (s & 15) * 4;
            float4 kv = *(const float4*)(Kp + (size_t)(j0 + j) * H + c4);
            sKT[(c4 + 0) * SKT_LD + j] = kv.x;
            sKT[(c4 + 1) * SKT_LD + j] = kv.y;
            sKT[(c4 + 2) * SKT_LD + j] = kv.z;
            sKT[(c4 + 3) * SKT_LD + j] = kv.w;
        }
        __syncthreads();
        float acc[4][4];
        #pragma unroll
        for (int i = 0; i < 4; i++)
            #pragma unroll
            for (int j = 0; j < 4; j++) acc[i][j] = 0.0f;
        #pragma unroll 4
        for (int k = 0; k < DH; k++) {
            float qv[4];
            #pragma unroll
            for (int i = 0; i < 4; i++) qv[i] = sQ[(tr * 4 + i) * SQ_LD + k];
            float4 kv = *(const float4*)&sKT[k * SKT_LD + tc * 4];
            #pragma unroll
            for (int i = 0; i < 4; i++) {
                acc[i][0] = fmaf(qv[i], kv.x, acc[i][0]);
                acc[i][1] = fmaf(qv[i], kv.y, acc[i][1]);
                acc[i][2] = fmaf(qv[i], kv.z, acc[i][2]);
                acc[i][3] = fmaf(qv[i], kv.w, acc[i][3]);
            }
        }
        #pragma unroll
        for (int i = 0; i < 4; i++)
            #pragma unroll
            for (int j = 0; j < 4; j++)
                sS[(tr * 4 + i) * SS_LD + j0 + tc * 4 + j] = acc[i][j] * scale;
    }
    __syncthreads();

    // ---- phase 2: softmax (one warp per row, 4 rows per warp) ----
    {
        int warp = tid >> 5, lane = tid & 31;
        for (int rr = 0; rr < 4; rr++) {
            float* srow = &sS[(warp + rr * 8) * SS_LD];
            float m = -1e30f;
            for (int t = lane; t < SEQ; t += 32) m = fmaxf(m, srow[t]);
            #pragma unroll
            for (int o = 16; o; o >>= 1) m = fmaxf(m, __shfl_xor_sync(0xffffffffu, m, o));
            float ssum = 0.0f;
            for (int t = lane; t < SEQ; t += 32) {
                float e = fexp(srow[t] - m);
                srow[t] = e;
                ssum += e;
            }
            #pragma unroll
            for (int o = 16; o; o >>= 1) ssum += __shfl_xor_sync(0xffffffffu, ssum, o);
            float inv = 1.0f / ssum;
            for (int t = lane; t < SEQ; t += 32) srow[t] *= inv;
        }
    }
    __syncthreads();

    // ---- phase 3: write weights (coalesced, once) ----
    {
        float* Wrow = Wout + ((size_t)(b * NH + h) * SEQ + q0) * SEQ;
        for (int s = tid; s < QT * 256; s += 256) {
            int r = s >> 8, c4 = (s & 255) * 4;
            *(float4*)(Wrow + (size_t)r * SEQ + c4) =
                *(const float4*)&sS[r * SS_LD + c4];
        }
    }

    // ---- phase 4: ctx = P @ V ----
    float acc2[4][2];
    #pragma unroll
    for (int i = 0; i < 4; i++) { acc2[i][0] = 0.0f; acc2[i][1] = 0.0f; }
    for (int kt = 0; kt < 8; kt++) {
        const int j0 = kt * 128;
        __syncthreads();
        for (int s = tid; s < 128 * 16; s += 256) {
            int r = s >> 4, c4 = (s & 15) * 4;
            *(float4*)&sV[r * SV_LD + c4] =
                *(const float4*)(Vp + (size_t)(j0 + r) * H + c4);
        }
        __syncthreads();
        #pragma unroll 4
        for (int kk = 0; kk < 128; kk++) {
            float2 vv = *(const float2*)&sV[kk * SV_LD + tc * 2];
            #pragma unroll
            for (int i = 0; i < 4; i++) {
                float p = sS[(tr * 4 + i) * SS_LD + j0 + kk];
                acc2[i][0] = fmaf(p, vv.x, acc2[i][0]);
                acc2[i][1] = fmaf(p, vv.y, acc2[i][1]);
            }
        }
    }
    #pragma unroll
    for (int i = 0; i < 4; i++) {
        size_t row = (size_t)b * SEQ + q0 + tr * 4 + i;
        float2 o; o.x = acc2[i][0]; o.y = acc2[i][1];
        *(float2*)(Ctx + row * H + h * DH + tc * 2) = o;
    }
}

// ---------------- launch ---------------------------------------------------
extern "C" void kernel_launch(void* const* d_in, const int* in_sizes, int n_in,
                              void* d_out, int out_size)
{
    const float* x   = (const float*)d_in[0];
    const float* wq  = (const float*)d_in[1];
    const float* bq  = (const float*)d_in[2];
    const float* wk  = (const float*)d_in[3];
    const float* bk  = (const float*)d_in[4];
    const float* wv  = (const float*)d_in[5];
    const float* bv  = (const float*)d_in[6];
    const float* wo  = (const float*)d_in[7];
    const float* bo  = (const float*)d_in[8];
    const float* w1  = (const float*)d_in[9];
    const float* b1  = (const float*)d_in[10];
    const float* w2  = (const float*)d_in[11];
    const float* b2  = (const float*)d_in[12];
    const float* g1  = (const float*)d_in[13];
    const float* be1 = (const float*)d_in[14];
    const float* g2  = (const float*)d_in[15];
    const float* be2 = (const float*)d_in[16];

    float* out_x = (float*)d_out;                 // (B,N,H)
    float* out_w = (float*)d_out + X_ELEMS;       // (B,NH,N,N)

    float *px1, *pq, *pk, *pv, *pctx, *pxres, *px2, *ph;
    cudaGetSymbolAddress((void**)&px1,  g_x1);
    cudaGetSymbolAddress((void**)&pq,   g_q);
    cudaGetSymbolAddress((void**)&pk,   g_k);
    cudaGetSymbolAddress((void**)&pv,   g_v);
    cudaGetSymbolAddress((void**)&pctx, g_ctx);
    cudaGetSymbolAddress((void**)&pxres,g_xres);
    cudaGetSymbolAddress((void**)&px2,  g_x2);
    cudaGetSymbolAddress((void**)&ph,   g_h);

    cudaFuncSetAttribute(attn_kernel,
        cudaFuncAttributeMaxDynamicSharedMemorySize, ATT_SMEM);

    // 1) LN1
    ln_kernel<<<ROWS, 256>>>(x, g1, be1, px1);

    // 2) QKV projections
    dim3 gH(H / 128, ROWS / 128);
    gemm_kernel<0><<<gH, 256>>>(px1, wq, bq, nullptr, pq, ROWS, H, H);
    gemm_kernel<0><<<gH, 256>>>(px1, wk, bk, nullptr, pk, ROWS, H, H);
    gemm_kernel<0><<<gH, 256>>>(px1, wv, bv, nullptr, pv, ROWS, H, H);

    // 3) attention: weights -> d_out, ctx -> scratch
    attn_kernel<<<dim3(SEQ / QT, NH, BB), 256, ATT_SMEM>>>(pq, pk, pv, out_w, pctx);

    // 4) output projection + residual(x)
    gemm_kernel<0><<<gH, 256>>>(pctx, wo, bo, x, pxres, ROWS, H, H);

    // 5) LN2
    ln_kernel<<<ROWS, 256>>>(pxres, g2, be2, px2);

    // 6) MLP
    gemm_kernel<1><<<dim3(FF / 128, ROWS / 128), 256>>>(px2, w1, b1, nullptr, ph, ROWS, FF, H);
    gemm_kernel<0><<<gH, 256>>>(ph, w2, b2, pxres, out_x, ROWS, H, FF);
}

// round 2
// speedup vs baseline: 1.9697x; 1.9697x over previous
#include <cuda_runtime.h>
#include <math.h>

#define H   768
#define NH  12
#define DH  64
#define FF  3072
#define BB  8
#define SEQ 1024
#define ROWS (BB*SEQ)                 // 8192
#define X_ELEMS ((size_t)ROWS*H)      // 6291456

// ---------------- scratch (static device allocations; no cudaMalloc) ------
__device__ float g_x1[ROWS*H];
__device__ float g_q [ROWS*H];
__device__ float g_k [ROWS*H];
__device__ float g_v [ROWS*H];
__device__ float g_ctx[ROWS*H];
__device__ float g_xres[ROWS*H];
__device__ float g_x2[ROWS*H];
__device__ float g_h [ROWS*FF];

// ---------------- fast exp (FMA pipe, avoids MUFU throughput wall) --------
__device__ __forceinline__ float fexp(float x) {
    x = fmaxf(x, -87.0f);
    float t  = x * 1.4426950408889634f;
    float fi = rintf(t);
    float z  = t - fi;
    float p  =            1.535336188319500e-4f;
    p = fmaf(p, z, 1.339887440266574e-3f);
    p = fmaf(p, z, 9.618437357674640e-3f);
    p = fmaf(p, z, 5.550332471162809e-2f);
    p = fmaf(p, z, 2.402264791363012e-1f);
    p = fmaf(p, z, 6.931472028550421e-1f);
    p = fmaf(p, z, 1.0f);
    return __int_as_float(((int)fi + 127) << 23) * p;
}

// ---------------- block reduce helper --------------------------------------
__device__ __forceinline__ float block_sum(float v, float* red) {
    #pragma unroll
    for (int o = 16; o; o >>= 1) v += __shfl_xor_sync(0xffffffffu, v, o);
    int w = threadIdx.x >> 5;
    if ((threadIdx.x & 31) == 0) red[w] = v;
    __syncthreads();
    float t = 0.0f;
    if (threadIdx.x < 32) {
        t = (threadIdx.x < 8) ? red[threadIdx.x] : 0.0f;
        #pragma unroll
        for (int o = 4; o; o >>= 1) t += __shfl_xor_sync(0xffffffffu, t, o);
        if (threadIdx.x == 0) red[0] = t;
    }
    __syncthreads();
    t = red[0];
    __syncthreads();
    return t;
}

// ---------------- layernorm: one block per row (H=768 = 256*3) ------------
__global__ __launch_bounds__(256) void ln_kernel(
    const float* __restrict__ x, const float* __restrict__ g,
    const float* __restrict__ b, float* __restrict__ y)
{
    __shared__ float red[8];
    int row = blockIdx.x;
    const float* xr = x + (size_t)row * H;
    int t = threadIdx.x;
    float v0 = xr[t], v1 = xr[t + 256], v2 = xr[t + 512];
    float mu = block_sum(v0 + v1 + v2, red) * (1.0f / H);
    float d0 = v0 - mu, d1 = v1 - mu, d2 = v2 - mu;
    float var = block_sum(d0*d0 + d1*d1 + d2*d2, red) * (1.0f / H);
    float rs = rsqrtf(var + 1e-6f);
    float* yr = y + (size_t)row * H;
    yr[t]       = d0 * rs * g[t]       + b[t];
    yr[t + 256] = d1 * rs * g[t + 256] + b[t + 256];
    yr[t + 512] = d2 * rs * g[t + 512] + b[t + 512];
}

// ================= TF32 tensor-core GEMM ===================================
// C[M,N] = A[M,K] @ W[K,N] + bias (+gelu) (+res)
// BM=128 BN=128 BK=32, 256 threads = 8 warps (4 along m, 2 along n).
// Warp tile 32x64 via mma.m16n8k8 (2 m-tiles x 8 n-tiles).
// SMEM: As[m][k] ld=36, Bs[k][n] ld=132 (both conflict-free for frag LDS).
#define ALD 36
#define BLD 132
#define G_SMEM ((2*128*ALD + 2*32*BLD) * 4)   // 70656 B

__device__ __forceinline__ unsigned f2tf32(float f) {
    unsigned u;
    asm("cvt.rna.tf32.f32 %0, %1;" : "=r"(u) : "f"(f));
    return u;
}

__device__ __forceinline__ void cp16(unsigned saddr, const void* g) {
    asm volatile("cp.async.cg.shared.global [%0], [%1], 16;\n"
                 :: "r"(saddr), "l"(g));
}

template<int ACT>
__global__ __launch_bounds__(256) void gemm_tc(
    const float* __restrict__ A, const float* __restrict__ W,
    const float* __restrict__ bias, const float* __restrict__ res,
    float* __restrict__ C, int M, int N, int K)
{
    extern __shared__ float sm[];
    float* As = sm;                 // [2][128][ALD]
    float* Bs = sm + 2 * 128 * ALD; // [2][32][BLD]

    const int tid  = threadIdx.x;
    const int wid  = tid >> 5;
    const int lane = tid & 31;
    const int g    = lane >> 2;   // group 0..7
    const int tg   = lane & 3;    // 0..3

    const int m0 = blockIdx.y * 128;
    const int n0 = blockIdx.x * 128;
    const int wm = (wid & 3) * 32;   // warp m offset in tile
    const int wn = (wid >> 2) * 64;  // warp n offset in tile

    // ---- cp.async source/dest mapping ----
    // A: 128 rows x 32 cols -> 1024 float4 chunks; thread handles 4.
    // B: 32 rows x 128 cols -> 1024 float4 chunks; thread handles 4.
    unsigned sbase = (unsigned)__cvta_generic_to_shared(sm);
    unsigned aS[4], bS[4];
    const float* aG[4];
    const float* bG[4];
    #pragma unroll
    for (int i = 0; i < 4; i++) {
        int c = tid + 256 * i;
        int ar = c >> 3, ac = (c & 7) * 4;
        aS[i] = sbase + (ar * ALD + ac) * 4;
        aG[i] = A + (size_t)(m0 + ar) * K + ac;
        int br = c >> 5, bc = (c & 31) * 4;
        bS[i] = sbase + (2 * 128 * ALD + br * BLD + bc) * 4;
        bG[i] = W + (size_t)br * N + n0 + bc;
    }
    const unsigned aStageB = 128 * ALD * 4;
    const unsigned bStageB = 32 * BLD * 4;

    float d[2][8][4];
    #pragma unroll
    for (int mt = 0; mt < 2; mt++)
        #pragma unroll
        for (int nt = 0; nt < 8; nt++)
            #pragma unroll
            for (int r = 0; r < 4; r++) d[mt][nt][r] = 0.0f;

    // prefetch stage 0
    #pragma unroll
    for (int i = 0; i < 4; i++) cp16(aS[i], aG[i]);
    #pragma unroll
    for (int i = 0; i < 4; i++) cp16(bS[i], bG[i]);
    asm volatile("cp.async.commit_group;\n");

    int s = 0;
    for (int k0 = 0; k0 < K; k0 += 32, s ^= 1) {
        if (k0 + 32 < K) {
            unsigned so = s ? 0u : 1u;
            #pragma unroll
            for (int i = 0; i < 4; i++)
                cp16(aS[i] + so * aStageB, aG[i] + k0 + 32);
            #pragma unroll
            for (int i = 0; i < 4; i++)
                cp16(bS[i] + so * bStageB, bG[i] + (size_t)(k0 + 32) * N);
            asm volatile("cp.async.commit_group;\n");
            asm volatile("cp.async.wait_group 1;\n");
        } else {
            asm volatile("cp.async.wait_group 0;\n");
        }
        __syncthreads();

        const float* Ab = As + s * 128 * ALD;
        const float* Bb = Bs + s * 32 * BLD;
        #pragma unroll
        for (int kk = 0; kk < 4; kk++) {
            const int kb = kk * 8 + tg;
            unsigned a[2][4], b[8][2];
            #pragma unroll
            for (int mt = 0; mt < 2; mt++) {
                const float* Ar = Ab + (wm + mt * 16 + g) * ALD;
                a[mt][0] = f2tf32(Ar[kb]);
                a[mt][1] = f2tf32(Ar[8 * ALD + kb]);
                a[mt][2] = f2tf32(Ar[kb + 4]);
                a[mt][3] = f2tf32(Ar[8 * ALD + kb + 4]);
            }
            #pragma unroll
            for (int nt = 0; nt < 8; nt++) {
                const float* Br = Bb + kb * BLD + wn + nt * 8 + g;
                b[nt][0] = f2tf32(Br[0]);
                b[nt][1] = f2tf32(Br[4 * BLD]);
            }
            #pragma unroll
            for (int mt = 0; mt < 2; mt++)
                #pragma unroll
                for (int nt = 0; nt < 8; nt++) {
                    asm volatile(
                        "mma.sync.aligned.m16n8k8.row.col.f32.tf32.tf32.f32 "
                        "{%0,%1,%2,%3}, {%4,%5,%6,%7}, {%8,%9}, {%0,%1,%2,%3};\n"
                        : "+f"(d[mt][nt][0]), "+f"(d[mt][nt][1]),
                          "+f"(d[mt][nt][2]), "+f"(d[mt][nt][3])
                        : "r"(a[mt][0]), "r"(a[mt][1]), "r"(a[mt][2]), "r"(a[mt][3]),
                          "r"(b[nt][0]), "r"(b[nt][1]));
                }
        }
        __syncthreads();
    }

    // ---- epilogue: bias (+gelu) (+res) ----
    #pragma unroll
    for (int mt = 0; mt < 2; mt++) {
        int r0 = m0 + wm + mt * 16 + g;
        #pragma unroll
        for (int nt = 0; nt < 8; nt++) {
            int c = n0 + wn + nt * 8 + 2 * tg;
            float b0 = bias[c], b1 = bias[c + 1];
            #pragma unroll
            for (int half = 0; half < 2; half++) {
                int row = r0 + half * 8;
                size_t base = (size_t)row * N + c;
                float v0 = d[mt][nt][2 * half]     + b0;
                float v1 = d[mt][nt][2 * half + 1] + b1;
                if (ACT == 1) {
                    v0 = 0.5f * v0 * (1.0f + erff(v0 * 0.70710678118654752f));
                    v1 = 0.5f * v1 * (1.0f + erff(v1 * 0.70710678118654752f));
                }
                if (res) { v0 += res[base]; v1 += res[base + 1]; }
                float2 o; o.x = v0; o.y = v1;
                *(float2*)(C + base) = o;
            }
        }
    }
}

// ---------------- fused attention (unchanged SIMT; tensorize next round) ---
#define QT 32
#define SQ_LD 68
#define SKT_LD 132
#define SV_LD 68
#define SS_LD 1028
#define ATT_SMEM ((QT*SQ_LD + DH*SKT_LD + 128*SV_LD + QT*SS_LD) * 4)

__global__ __launch_bounds__(256) void attn_kernel(
    const float* __restrict__ Q, const float* __restrict__ K,
    const float* __restrict__ V, float* __restrict__ Wout,
    float* __restrict__ Ctx)
{
    extern __shared__ float smm[];
    float* sQ  = smm;
    float* sKT = sQ  + QT * SQ_LD;
    float* sV  = sKT + DH * SKT_LD;
    float* sS  = sV  + 128 * SV_LD;

    const int tid = threadIdx.x;
    const int q0 = blockIdx.x * QT;
    const int h  = blockIdx.y;
    const int b  = blockIdx.z;
    const float scale = 0.03608439182435161f;  // 1/sqrt(768)

    const size_t head = (size_t)b * SEQ * H + (size_t)h * DH;
    const float* Qp = Q + head;
    const float* Kp = K + head;
    const float* Vp = V + head;

    for (int s = tid; s < QT * 16; s += 256) {
        int r = s >> 4, c4 = (s & 15) * 4;
        *(float4*)&sQ[r * SQ_LD + c4] =
            *(const float4*)(Qp + (size_t)(q0 + r) * H + c4);
    }

    const int tr = tid >> 5;
    const int tc = tid & 31;

    for (int jt = 0; jt < 8; jt++) {
        const int j0 = jt * 128;
        __syncthreads();
        for (int s = tid; s < 128 * 16; s += 256) {
            int j = s >> 4, c4 = (s & 15) * 4;
            float4 kv = *(const float4*)(Kp + (size_t)(j0 + j) * H + c4);
            sKT[(c4 + 0) * SKT_LD + j] = kv.x;
            sKT[(c4 + 1) * SKT_LD + j] = kv.y;
            sKT[(c4 + 2) * SKT_LD + j] = kv.z;
            sKT[(c4 + 3) * SKT_LD + j] = kv.w;
        }
        __syncthreads();
        float acc[4][4];
        #pragma unroll
        for (int i = 0; i < 4; i++)
            #pragma unroll
            for (int j = 0; j < 4; j++) acc[i][j] = 0.0f;
        #pragma unroll 4
        for (int k = 0; k < DH; k++) {
            float qv[4];
            #pragma unroll
            for (int i = 0; i < 4; i++) qv[i] = sQ[(tr * 4 + i) * SQ_LD + k];
            float4 kv = *(const float4*)&sKT[k * SKT_LD + tc * 4];
            #pragma unroll
            for (int i = 0; i < 4; i++) {
                acc[i][0] = fmaf(qv[i], kv.x, acc[i][0]);
                acc[i][1] = fmaf(qv[i], kv.y, acc[i][1]);
                acc[i][2] = fmaf(qv[i], kv.z, acc[i][2]);
                acc[i][3] = fmaf(qv[i], kv.w, acc[i][3]);
            }
        }
        #pragma unroll
        for (int i = 0; i < 4; i++)
            #pragma unroll
            for (int j = 0; j < 4; j++)
                sS[(tr * 4 + i) * SS_LD + j0 + tc * 4 + j] = acc[i][j] * scale;
    }
    __syncthreads();

    {
        int warp = tid >> 5, lane = tid & 31;
        for (int rr = 0; rr < 4; rr++) {
            float* srow = &sS[(warp + rr * 8) * SS_LD];
            float m = -1e30f;
            for (int t = lane; t < SEQ; t += 32) m = fmaxf(m, srow[t]);
            #pragma unroll
            for (int o = 16; o; o >>= 1) m = fmaxf(m, __shfl_xor_sync(0xffffffffu, m, o));
            float ssum = 0.0f;
            for (int t = lane; t < SEQ; t += 32) {
                float e = fexp(srow[t] - m);
                srow[t] = e;
                ssum += e;
            }
            #pragma unroll
            for (int o = 16; o; o >>= 1) ssum += __shfl_xor_sync(0xffffffffu, ssum, o);
            float inv = 1.0f / ssum;
            for (int t = lane; t < SEQ; t += 32) srow[t] *= inv;
        }
    }
    __syncthreads();

    {
        float* Wrow = Wout + ((size_t)(b * NH + h) * SEQ + q0) * SEQ;
        for (int s = tid; s < QT * 256; s += 256) {
            int r = s >> 8, c4 = (s & 255) * 4;
            *(float4*)(Wrow + (size_t)r * SEQ + c4) =
                *(const float4*)&sS[r * SS_LD + c4];
        }
    }

    float acc2[4][2];
    #pragma unroll
    for (int i = 0; i < 4; i++) { acc2[i][0] = 0.0f; acc2[i][1] = 0.0f; }
    for (int kt = 0; kt < 8; kt++) {
        const int j0 = kt * 128;
        __syncthreads();
        for (int s = tid; s < 128 * 16; s += 256) {
            int r = s >> 4, c4 = (s & 15) * 4;
            *(float4*)&sV[r * SV_LD + c4] =
                *(const float4*)(Vp + (size_t)(j0 + r) * H + c4);
        }
        __syncthreads();
        #pragma unroll 4
        for (int kk = 0; kk < 128; kk++) {
            float2 vv = *(const float2*)&sV[kk * SV_LD + tc * 2];
            #pragma unroll
            for (int i = 0; i < 4; i++) {
                float p = sS[(tr * 4 + i) * SS_LD + j0 + kk];
                acc2[i][0] = fmaf(p, vv.x, acc2[i][0]);
                acc2[i][1] = fmaf(p, vv.y, acc2[i][1]);
            }
        }
    }
    #pragma unroll
    for (int i = 0; i < 4; i++) {
        size_t row = (size_t)b * SEQ + q0 + tr * 4 + i;
        float2 o; o.x = acc2[i][0]; o.y = acc2[i][1];
        *(float2*)(Ctx + row * H + h * DH + tc * 2) = o;
    }
}

// ---------------- launch ---------------------------------------------------
extern "C" void kernel_launch(void* const* d_in, const int* in_sizes, int n_in,
                              void* d_out, int out_size)
{
    const float* x   = (const float*)d_in[0];
    const float* wq  = (const float*)d_in[1];
    const float* bq  = (const float*)d_in[2];
    const float* wk  = (const float*)d_in[3];
    const float* bk  = (const float*)d_in[4];
    const float* wv  = (const float*)d_in[5];
    const float* bv  = (const float*)d_in[6];
    const float* wo  = (const float*)d_in[7];
    const float* bo  = (const float*)d_in[8];
    const float* w1  = (const float*)d_in[9];
    const float* b1  = (const float*)d_in[10];
    const float* w2  = (const float*)d_in[11];
    const float* b2  = (const float*)d_in[12];
    const float* g1  = (const float*)d_in[13];
    const float* be1 = (const float*)d_in[14];
    const float* g2  = (const float*)d_in[15];
    const float* be2 = (const float*)d_in[16];

    float* out_x = (float*)d_out;
    float* out_w = (float*)d_out + X_ELEMS;

    float *px1, *pq, *pk, *pv, *pctx, *pxres, *px2, *ph;
    cudaGetSymbolAddress((void**)&px1,  g_x1);
    cudaGetSymbolAddress((void**)&pq,   g_q);
    cudaGetSymbolAddress((void**)&pk,   g_k);
    cudaGetSymbolAddress((void**)&pv,   g_v);
    cudaGetSymbolAddress((void**)&pctx, g_ctx);
    cudaGetSymbolAddress((void**)&pxres,g_xres);
    cudaGetSymbolAddress((void**)&px2,  g_x2);
    cudaGetSymbolAddress((void**)&ph,   g_h);

    cudaFuncSetAttribute(attn_kernel,
        cudaFuncAttributeMaxDynamicSharedMemorySize, ATT_SMEM);
    cudaFuncSetAttribute(gemm_tc<0>,
        cudaFuncAttributeMaxDynamicSharedMemorySize, G_SMEM);
    cudaFuncSetAttribute(gemm_tc<1>,
        cudaFuncAttributeMaxDynamicSharedMemorySize, G_SMEM);

    // 1) LN1
    ln_kernel<<<ROWS, 256>>>(x, g1, be1, px1);

    // 2) QKV projections (tf32 tensor cores)
    dim3 gH(H / 128, ROWS / 128);
    gemm_tc<0><<<gH, 256, G_SMEM>>>(px1, wq, bq, nullptr, pq, ROWS, H, H);
    gemm_tc<0><<<gH, 256, G_SMEM>>>(px1, wk, bk, nullptr, pk, ROWS, H, H);
    gemm_tc<0><<<gH, 256, G_SMEM>>>(px1, wv, bv, nullptr, pv, ROWS, H, H);

    // 3) attention: weights -> d_out, ctx -> scratch
    attn_kernel<<<dim3(SEQ / QT, NH, BB), 256, ATT_SMEM>>>(pq, pk, pv, out_w, pctx);

    // 4) output projection + residual(x)
    gemm_tc<0><<<gH, 256, G_SMEM>>>(pctx, wo, bo, x, pxres, ROWS, H, H);

    // 5) LN2
    ln_kernel<<<ROWS, 256>>>(pxres, g2, be2, px2);

    // 6) MLP
    gemm_tc<1><<<dim3(FF / 128, ROWS / 128), 256, G_SMEM>>>(px2, w1, b1, nullptr, ph, ROWS, FF, H);
    gemm_tc<0><<<gH, 256, G_SMEM>>>(ph, w2, b2, pxres, out_x, ROWS, H, FF);
}

// round 3
// speedup vs baseline: 3.2470x; 1.6485x over previous
#include <cuda_runtime.h>
#include <math.h>

#define H   768
#define NH  12
#define DH  64
#define FF  3072
#define BB  8
#define SEQ 1024
#define ROWS (BB*SEQ)                 // 8192
#define X_ELEMS ((size_t)ROWS*H)      // 6291456

// ---------------- scratch (static device allocations; no cudaMalloc) ------
__device__ float g_x1[ROWS*H];
__device__ float g_q [ROWS*H];
__device__ float g_k [ROWS*H];
__device__ float g_v [ROWS*H];
__device__ float g_ctx[ROWS*H];
__device__ float g_xres[ROWS*H];
__device__ float g_x2[ROWS*H];
__device__ float g_h [ROWS*FF];
// pre-rounded (tf32) weights
__device__ float g_wq[H*H];
__device__ float g_wk[H*H];
__device__ float g_wv[H*H];
__device__ float g_wo[H*H];
__device__ float g_w1[H*FF];
__device__ float g_w2[FF*H];

// ---------------- tf32 round helper ----------------------------------------
__device__ __forceinline__ float rtf32(float f) {
    unsigned u;
    asm("cvt.rna.tf32.f32 %0, %1;" : "=r"(u) : "f"(f));
    return __uint_as_float(u);
}

__device__ __forceinline__ void cp16(unsigned saddr, const void* g) {
    asm volatile("cp.async.cg.shared.global [%0], [%1], 16;\n"
                 :: "r"(saddr), "l"(g));
}

__device__ __forceinline__ void mma8(float* d, const unsigned* a, const unsigned* b) {
    asm volatile(
        "mma.sync.aligned.m16n8k8.row.col.f32.tf32.tf32.f32 "
        "{%0,%1,%2,%3}, {%4,%5,%6,%7}, {%8,%9}, {%0,%1,%2,%3};\n"
        : "+f"(d[0]), "+f"(d[1]), "+f"(d[2]), "+f"(d[3])
        : "r"(a[0]), "r"(a[1]), "r"(a[2]), "r"(a[3]), "r"(b[0]), "r"(b[1]));
}

// ---------------- fast exp (FMA pipe) --------------------------------------
__device__ __forceinline__ float fexp(float x) {
    x = fmaxf(x, -87.0f);
    float t  = x * 1.4426950408889634f;
    float fi = rintf(t);
    float z  = t - fi;
    float p  =            1.535336188319500e-4f;
    p = fmaf(p, z, 1.339887440266574e-3f);
    p = fmaf(p, z, 9.618437357674640e-3f);
    p = fmaf(p, z, 5.550332471162809e-2f);
    p = fmaf(p, z, 2.402264791363012e-1f);
    p = fmaf(p, z, 6.931472028550421e-1f);
    p = fmaf(p, z, 1.0f);
    return __int_as_float(((int)fi + 127) << 23) * p;
}

// ---------------- weight pre-round ------------------------------------------
__global__ void round_kernel(const float4* __restrict__ s, float4* __restrict__ d, int n4) {
    for (int i = blockIdx.x * blockDim.x + threadIdx.x; i < n4;
         i += gridDim.x * blockDim.x) {
        float4 v = s[i];
        v.x = rtf32(v.x); v.y = rtf32(v.y); v.z = rtf32(v.z); v.w = rtf32(v.w);
        d[i] = v;
    }
}

// ---------------- block reduce helper --------------------------------------
__device__ __forceinline__ float block_sum(float v, float* red) {
    #pragma unroll
    for (int o = 16; o; o >>= 1) v += __shfl_xor_sync(0xffffffffu, v, o);
    int w = threadIdx.x >> 5;
    if ((threadIdx.x & 31) == 0) red[w] = v;
    __syncthreads();
    float t = 0.0f;
    if (threadIdx.x < 32) {
        t = (threadIdx.x < 8) ? red[threadIdx.x] : 0.0f;
        #pragma unroll
        for (int o = 4; o; o >>= 1) t += __shfl_xor_sync(0xffffffffu, t, o);
        if (threadIdx.x == 0) red[0] = t;
    }
    __syncthreads();
    t = red[0];
    __syncthreads();
    return t;
}

// ---------------- layernorm (ROUND: emit tf32-rounded output) --------------
template<int ROUND>
__global__ __launch_bounds__(256) void ln_kernel(
    const float* __restrict__ x, const float* __restrict__ g,
    const float* __restrict__ b, float* __restrict__ y)
{
    __shared__ float red[8];
    int row = blockIdx.x;
    const float* xr = x + (size_t)row * H;
    int t = threadIdx.x;
    float v0 = xr[t], v1 = xr[t + 256], v2 = xr[t + 512];
    float mu = block_sum(v0 + v1 + v2, red) * (1.0f / H);
    float d0 = v0 - mu, d1 = v1 - mu, d2 = v2 - mu;
    float var = block_sum(d0*d0 + d1*d1 + d2*d2, red) * (1.0f / H);
    float rs = rsqrtf(var + 1e-6f);
    float* yr = y + (size_t)row * H;
    float o0 = d0 * rs * g[t]       + b[t];
    float o1 = d1 * rs * g[t + 256] + b[t + 256];
    float o2 = d2 * rs * g[t + 512] + b[t + 512];
    if (ROUND) { o0 = rtf32(o0); o1 = rtf32(o1); o2 = rtf32(o2); }
    yr[t] = o0; yr[t + 256] = o1; yr[t + 512] = o2;
}

// ================= TF32 tensor-core GEMM (inputs pre-rounded) ==============
#define ALD 36
#define BLD 132
#define G_SMEM ((2*128*ALD + 2*32*BLD) * 4)   // 70656 B

template<int ACT, int ROUND>
__global__ __launch_bounds__(256) void gemm_tc(
    const float* __restrict__ A, const float* __restrict__ W,
    const float* __restrict__ bias, const float* __restrict__ res,
    float* __restrict__ C, int M, int N, int K)
{
    extern __shared__ float sm[];
    float* As = sm;                 // [2][128][ALD]
    float* Bs = sm + 2 * 128 * ALD; // [2][32][BLD]

    const int tid  = threadIdx.x;
    const int wid  = tid >> 5;
    const int lane = tid & 31;
    const int g    = lane >> 2;
    const int tg   = lane & 3;

    const int m0 = blockIdx.y * 128;
    const int n0 = blockIdx.x * 128;
    const int wm = (wid & 3) * 32;
    const int wn = (wid >> 2) * 64;

    unsigned sbase = (unsigned)__cvta_generic_to_shared(sm);
    unsigned aS[4], bS[4];
    const float* aG[4];
    const float* bG[4];
    #pragma unroll
    for (int i = 0; i < 4; i++) {
        int c = tid + 256 * i;
        int ar = c >> 3, ac = (c & 7) * 4;
        aS[i] = sbase + (ar * ALD + ac) * 4;
        aG[i] = A + (size_t)(m0 + ar) * K + ac;
        int br = c >> 5, bc = (c & 31) * 4;
        bS[i] = sbase + (2 * 128 * ALD + br * BLD + bc) * 4;
        bG[i] = W + (size_t)br * N + n0 + bc;
    }
    const unsigned aStageB = 128 * ALD * 4;
    const unsigned bStageB = 32 * BLD * 4;

    float d[2][8][4];
    #pragma unroll
    for (int mt = 0; mt < 2; mt++)
        #pragma unroll
        for (int nt = 0; nt < 8; nt++)
            #pragma unroll
            for (int r = 0; r < 4; r++) d[mt][nt][r] = 0.0f;

    #pragma unroll
    for (int i = 0; i < 4; i++) cp16(aS[i], aG[i]);
    #pragma unroll
    for (int i = 0; i < 4; i++) cp16(bS[i], bG[i]);
    asm volatile("cp.async.commit_group;\n");

    int s = 0;
    for (int k0 = 0; k0 < K; k0 += 32, s ^= 1) {
        if (k0 + 32 < K) {
            unsigned so = s ? 0u : 1u;
            #pragma unroll
            for (int i = 0; i < 4; i++)
                cp16(aS[i] + so * aStageB, aG[i] + k0 + 32);
            #pragma unroll
            for (int i = 0; i < 4; i++)
                cp16(bS[i] + so * bStageB, bG[i] + (size_t)(k0 + 32) * N);
            asm volatile("cp.async.commit_group;\n");
            asm volatile("cp.async.wait_group 1;\n");
        } else {
            asm volatile("cp.async.wait_group 0;\n");
        }
        __syncthreads();

        const float* Ab = As + s * 128 * ALD;
        const float* Bb = Bs + s * 32 * BLD;
        #pragma unroll
        for (int kk = 0; kk < 4; kk++) {
            const int kb = kk * 8 + tg;
            unsigned a[2][4], b[8][2];
            #pragma unroll
            for (int mt = 0; mt < 2; mt++) {
                const float* Ar = Ab + (wm + mt * 16 + g) * ALD;
                a[mt][0] = __float_as_uint(Ar[kb]);
                a[mt][1] = __float_as_uint(Ar[8 * ALD + kb]);
                a[mt][2] = __float_as_uint(Ar[kb + 4]);
                a[mt][3] = __float_as_uint(Ar[8 * ALD + kb + 4]);
            }
            #pragma unroll
            for (int nt = 0; nt < 8; nt++) {
                const float* Br = Bb + kb * BLD + wn + nt * 8 + g;
                b[nt][0] = __float_as_uint(Br[0]);
                b[nt][1] = __float_as_uint(Br[4 * BLD]);
            }
            #pragma unroll
            for (int mt = 0; mt < 2; mt++)
                #pragma unroll
                for (int nt = 0; nt < 8; nt++)
                    mma8(d[mt][nt], a[mt], b[nt]);
        }
        __syncthreads();
    }

    #pragma unroll
    for (int mt = 0; mt < 2; mt++) {
        int r0 = m0 + wm + mt * 16 + g;
        #pragma unroll
        for (int nt = 0; nt < 8; nt++) {
            int c = n0 + wn + nt * 8 + 2 * tg;
            float b0 = bias[c], b1 = bias[c + 1];
            #pragma unroll
            for (int half = 0; half < 2; half++) {
                int row = r0 + half * 8;
                size_t base = (size_t)row * N + c;
                float v0 = d[mt][nt][2 * half]     + b0;
                float v1 = d[mt][nt][2 * half + 1] + b1;
                if (ACT == 1) {
                    v0 = 0.5f * v0 * (1.0f + erff(v0 * 0.70710678118654752f));
                    v1 = 0.5f * v1 * (1.0f + erff(v1 * 0.70710678118654752f));
                }
                if (res) { v0 += res[base]; v1 += res[base + 1]; }
                if (ROUND) { v0 = rtf32(v0); v1 = rtf32(v1); }
                float2 o; o.x = v0; o.y = v1;
                *(float2*)(C + base) = o;
            }
        }
    }
}

// ================= tensor-core fused attention ==============================
// Block = (q-tile 32, h, b). 256 threads = 8 warps.
// Phase1: S = Q K^T * scale via mma (K streamed 128-row chunks, dbl-buffered)
// Phase2: softmax in SMEM. Phase3: write weights + round P to tf32.
// Phase4: ctx = P V via mma (V streamed, dbl-buffered).
#define KV_LD 68
#define SS_LD 1028
#define ATT_SMEM ((32*KV_LD + 2*128*KV_LD + 32*SS_LD) * 4)   // 210048 B

__device__ __forceinline__ void load_kv(unsigned skv, const float* gp,
                                        int chunk, int buf, int tid) {
    #pragma unroll
    for (int i = 0; i < 8; i++) {
        int idx = tid + 256 * i;
        int r = idx >> 4, c = (idx & 15) * 4;
        cp16(skv + (unsigned)(buf * 128 * KV_LD + r * KV_LD + c) * 4,
             gp + (size_t)(chunk * 128 + r) * H + c);
    }
}

__global__ __launch_bounds__(256) void attn_tc(
    const float* __restrict__ Q, const float* __restrict__ K,
    const float* __restrict__ V, float* __restrict__ Wout,
    float* __restrict__ Ctx)
{
    extern __shared__ float sm[];
    float* sQ  = sm;                          // [32][68]
    float* sKV = sQ + 32 * KV_LD;             // [2][128][68]
    float* sS  = sKV + 2 * 128 * KV_LD;       // [32][1028]

    const int tid  = threadIdx.x;
    const int wid  = tid >> 5;
    const int lane = tid & 31;
    const int g    = lane >> 2;
    const int tg   = lane & 3;
    const int q0   = blockIdx.x * 32;
    const int h    = blockIdx.y;
    const int b    = blockIdx.z;
    const float scale = 0.03608439182435161f;   // 1/sqrt(768)

    const size_t head = (size_t)b * SEQ * H + (size_t)h * DH;
    const float* Qp = Q + head + (size_t)q0 * H;
    const float* Kp = K + head;
    const float* Vp = V + head;

    unsigned sQb  = (unsigned)__cvta_generic_to_shared(sQ);
    unsigned sKVb = (unsigned)__cvta_generic_to_shared(sKV);

    // prefetch Q tile + K chunks 0,1
    #pragma unroll
    for (int i = 0; i < 2; i++) {
        int idx = tid + 256 * i;
        int r = idx >> 4, c = (idx & 15) * 4;
        cp16(sQb + (unsigned)(r * KV_LD + c) * 4, Qp + (size_t)r * H + c);
    }
    load_kv(sKVb, Kp, 0, 0, tid);
    asm volatile("cp.async.commit_group;\n");
    load_kv(sKVb, Kp, 1, 1, tid);
    asm volatile("cp.async.commit_group;\n");
    asm volatile("cp.async.wait_group 1;\n");
    __syncthreads();

    // Q fragments in registers (already tf32-rounded bits)
    unsigned qf[2][8][4];
    #pragma unroll
    for (int ks = 0; ks < 8; ks++)
        #pragma unroll
        for (int mt = 0; mt < 2; mt++) {
            const float* Qr = sQ + (g + mt * 16) * KV_LD + ks * 8 + tg;
            qf[mt][ks][0] = __float_as_uint(Qr[0]);
            qf[mt][ks][1] = __float_as_uint(Qr[8 * KV_LD]);
            qf[mt][ks][2] = __float_as_uint(Qr[4]);
            qf[mt][ks][3] = __float_as_uint(Qr[8 * KV_LD + 4]);
        }

    // ---- phase 1: scores ----
    for (int jt = 0; jt < 8; jt++) {
        const float* Kb = sKV + (jt & 1) * 128 * KV_LD;
        float acc[2][2][4];
        #pragma unroll
        for (int mt = 0; mt < 2; mt++)
            #pragma unroll
            for (int nt = 0; nt < 2; nt++)
                #pragma unroll
                for (int r = 0; r < 4; r++) acc[mt][nt][r] = 0.0f;
        #pragma unroll
        for (int ks = 0; ks < 8; ks++) {
            unsigned bf[2][2];
            #pragma unroll
            for (int nt = 0; nt < 2; nt++) {
                const float* Kr = Kb + (wid * 16 + nt * 8 + g) * KV_LD + ks * 8 + tg;
                bf[nt][0] = __float_as_uint(Kr[0]);
                bf[nt][1] = __float_as_uint(Kr[4]);
            }
            #pragma unroll
            for (int mt = 0; mt < 2; mt++)
                #pragma unroll
                for (int nt = 0; nt < 2; nt++)
                    mma8(acc[mt][nt], qf[mt][ks], bf[nt]);
        }
        // store to sS (scaled)
        #pragma unroll
        for (int mt = 0; mt < 2; mt++)
            #pragma unroll
            for (int nt = 0; nt < 2; nt++) {
                int col = jt * 128 + wid * 16 + nt * 8 + 2 * tg;
                int r1 = g + mt * 16;
                float2 o0; o0.x = acc[mt][nt][0] * scale; o0.y = acc[mt][nt][1] * scale;
                float2 o1; o1.x = acc[mt][nt][2] * scale; o1.y = acc[mt][nt][3] * scale;
                *(float2*)&sS[r1 * SS_LD + col]       = o0;
                *(float2*)&sS[(r1 + 8) * SS_LD + col] = o1;
            }
        __syncthreads();
        if (jt < 6) {
            load_kv(sKVb, Kp, jt + 2, jt & 1, tid);
            asm volatile("cp.async.commit_group;\n");
        }
        if (jt < 7) {
            if (jt < 6) asm volatile("cp.async.wait_group 1;\n");
            else        asm volatile("cp.async.wait_group 0;\n");
            __syncthreads();
        }
    }

    // prefetch V chunk 0 (overlaps softmax)
    load_kv(sKVb, Vp, 0, 0, tid);
    asm volatile("cp.async.commit_group;\n");

    // ---- phase 2: softmax (warp per row, 4 rows per warp) ----
    {
        for (int rr = 0; rr < 4; rr++) {
            float* srow = &sS[(wid + rr * 8) * SS_LD];
            float m = -1e30f;
            for (int t = lane; t < SEQ; t += 32) m = fmaxf(m, srow[t]);
            #pragma unroll
            for (int o = 16; o; o >>= 1) m = fmaxf(m, __shfl_xor_sync(0xffffffffu, m, o));
            float ssum = 0.0f;
            for (int t = lane; t < SEQ; t += 32) {
                float e = fexp(srow[t] - m);
                srow[t] = e;
                ssum += e;
            }
            #pragma unroll
            for (int o = 16; o; o >>= 1) ssum += __shfl_xor_sync(0xffffffffu, ssum, o);
            float inv = 1.0f / ssum;
            for (int t = lane; t < SEQ; t += 32) srow[t] *= inv;
        }
    }
    __syncthreads();

    // ---- phase 3: write weights (f32) + round P in smem to tf32 ----
    {
        float* Wrow = Wout + ((size_t)(b * NH + h) * SEQ + q0) * SEQ;
        for (int s = tid; s < 32 * 256; s += 256) {
            int r = s >> 8, c4 = (s & 255) * 4;
            float4 v = *(const float4*)&sS[r * SS_LD + c4];
            *(float4*)(Wrow + (size_t)r * SEQ + c4) = v;
            v.x = rtf32(v.x); v.y = rtf32(v.y); v.z = rtf32(v.z); v.w = rtf32(v.w);
            *(float4*)&sS[r * SS_LD + c4] = v;
        }
    }
    __syncthreads();

    load_kv(sKVb, Vp, 1, 1, tid);
    asm volatile("cp.async.commit_group;\n");
    asm volatile("cp.async.wait_group 1;\n");
    __syncthreads();

    // ---- phase 4: ctx = P @ V ----
    float acc2[2][4];
    #pragma unroll
    for (int mt = 0; mt < 2; mt++)
        #pragma unroll
        for (int r = 0; r < 4; r++) acc2[mt][r] = 0.0f;

    for (int kt = 0; kt < 8; kt++) {
        const float* Vb = sKV + (kt & 1) * 128 * KV_LD;
        #pragma unroll 4
        for (int ks = 0; ks < 16; ks++) {
            int kcol = kt * 128 + ks * 8;
            unsigned bf[2];
            bf[0] = __float_as_uint(Vb[(ks * 8 + tg)     * KV_LD + wid * 8 + g]);
            bf[1] = __float_as_uint(Vb[(ks * 8 + tg + 4) * KV_LD + wid * 8 + g]);
            #pragma unroll
            for (int mt = 0; mt < 2; mt++) {
                unsigned af[4];
                const float* Pr = sS + (g + mt * 16) * SS_LD + kcol + tg;
                af[0] = __float_as_uint(Pr[0]);
                af[1] = __float_as_uint(Pr[8 * SS_LD]);
                af[2] = __float_as_uint(Pr[4]);
                af[3] = __float_as_uint(Pr[8 * SS_LD + 4]);
                mma8(acc2[mt], af, bf);
            }
        }
        __syncthreads();
        if (kt < 6) {
            load_kv(sKVb, Vp, kt + 2, kt & 1, tid);
            asm volatile("cp.async.commit_group;\n");
        }
        if (kt < 7) {
            if (kt < 6) asm volatile("cp.async.wait_group 1;\n");
            else        asm volatile("cp.async.wait_group 0;\n");
            __syncthreads();
        }
    }

    // write ctx (tf32-rounded: feeds the wo GEMM)
    #pragma unroll
    for (int mt = 0; mt < 2; mt++)
        #pragma unroll
        for (int half = 0; half < 2; half++) {
            int row = q0 + g + mt * 16 + half * 8;
            int col = h * DH + wid * 8 + 2 * tg;
            float2 o;
            o.x = rtf32(acc2[mt][2 * half]);
            o.y = rtf32(acc2[mt][2 * half + 1]);
            *(float2*)(Ctx + ((size_t)b * SEQ + row) * H + col) = o;
        }
}

// ---------------- launch ---------------------------------------------------
extern "C" void kernel_launch(void* const* d_in, const int* in_sizes, int n_in,
                              void* d_out, int out_size)
{
    const float* x   = (const float*)d_in[0];
    const float* wq  = (const float*)d_in[1];
    const float* bq  = (const float*)d_in[2];
    const float* wk  = (const float*)d_in[3];
    const float* bk  = (const float*)d_in[4];
    const float* wv  = (const float*)d_in[5];
    const float* bv  = (const float*)d_in[6];
    const float* wo  = (const float*)d_in[7];
    const float* bo  = (const float*)d_in[8];
    const float* w1  = (const float*)d_in[9];
    const float* b1  = (const float*)d_in[10];
    const float* w2  = (const float*)d_in[11];
    const float* b2  = (const float*)d_in[12];
    const float* g1  = (const float*)d_in[13];
    const float* be1 = (const float*)d_in[14];
    const float* g2  = (const float*)d_in[15];
    const float* be2 = (const float*)d_in[16];

    float* out_x = (float*)d_out;
    float* out_w = (float*)d_out + X_ELEMS;

    float *px1, *pq, *pk, *pv, *pctx, *pxres, *px2, *ph;
    float *pwq, *pwk, *pwv, *pwo, *pw1, *pw2;
    cudaGetSymbolAddress((void**)&px1,  g_x1);
    cudaGetSymbolAddress((void**)&pq,   g_q);
    cudaGetSymbolAddress((void**)&pk,   g_k);
    cudaGetSymbolAddress((void**)&pv,   g_v);
    cudaGetSymbolAddress((void**)&pctx, g_ctx);
    cudaGetSymbolAddress((void**)&pxres,g_xres);
    cudaGetSymbolAddress((void**)&px2,  g_x2);
    cudaGetSymbolAddress((void**)&ph,   g_h);
    cudaGetSymbolAddress((void**)&pwq,  g_wq);
    cudaGetSymbolAddress((void**)&pwk,  g_wk);
    cudaGetSymbolAddress((void**)&pwv,  g_wv);
    cudaGetSymbolAddress((void**)&pwo,  g_wo);
    cudaGetSymbolAddress((void**)&pw1,  g_w1);
    cudaGetSymbolAddress((void**)&pw2,  g_w2);

    cudaFuncSetAttribute(attn_tc,
        cudaFuncAttributeMaxDynamicSharedMemorySize, ATT_SMEM);
    cudaFuncSetAttribute(gemm_tc<0,0>,
        cudaFuncAttributeMaxDynamicSharedMemorySize, G_SMEM);
    cudaFuncSetAttribute(gemm_tc<0,1>,
        cudaFuncAttributeMaxDynamicSharedMemorySize, G_SMEM);
    cudaFuncSetAttribute(gemm_tc<1,1>,
        cudaFuncAttributeMaxDynamicSharedMemorySize, G_SMEM);

    // 0) pre-round weights to tf32
    round_kernel<<<1184, 256>>>((const float4*)wq, (float4*)pwq, H*H/4);
    round_kernel<<<1184, 256>>>((const float4*)wk, (float4*)pwk, H*H/4);
    round_kernel<<<1184, 256>>>((const float4*)wv, (float4*)pwv, H*H/4);
    round_kernel<<<1184, 256>>>((const float4*)wo, (float4*)pwo, H*H/4);
    round_kernel<<<1184, 256>>>((const float4*)w1, (float4*)pw1, H*FF/4);
    round_kernel<<<1184, 256>>>((const float4*)w2, (float4*)pw2, FF*H/4);

    // 1) LN1 (rounded output -> QKV gemms)
    ln_kernel<1><<<ROWS, 256>>>(x, g1, be1, px1);

    // 2) QKV projections (rounded outputs -> attention mma)
    dim3 gH(H / 128, ROWS / 128);
    gemm_tc<0,1><<<gH, 256, G_SMEM>>>(px1, pwq, bq, nullptr, pq, ROWS, H, H);
    gemm_tc<0,1><<<gH, 256, G_SMEM>>>(px1, pwk, bk, nullptr, pk, ROWS, H, H);
    gemm_tc<0,1><<<gH, 256, G_SMEM>>>(px1, pwv, bv, nullptr, pv, ROWS, H, H);

    // 3) attention: weights -> d_out, ctx (rounded) -> scratch
    attn_tc<<<dim3(SEQ / 32, NH, BB), 256, ATT_SMEM>>>(pq, pk, pv, out_w, pctx);

    // 4) output projection + residual(x) (full f32 out)
    gemm_tc<0,0><<<gH, 256, G_SMEM>>>(pctx, pwo, bo, x, pxres, ROWS, H, H);

    // 5) LN2 (rounded -> w1 gemm)
    ln_kernel<1><<<ROWS, 256>>>(pxres, g2, be2, px2);

    // 6) MLP (h rounded -> w2 gemm; final out f32 + residual)
    gemm_tc<1,1><<<dim3(FF / 128, ROWS / 128), 256, G_SMEM>>>(px2, pw1, b1, nullptr, ph, ROWS, FF, H);
    gemm_tc<0,0><<<gH, 256, G_SMEM>>>(ph, pw2, b2, pxres, out_x, ROWS, H, FF);
}

// round 4
// speedup vs baseline: 3.3820x; 1.0416x over previous
#include <cuda_runtime.h>
#include <math.h>

#define H   768
#define NH  12
#define DH  64
#define FF  3072
#define BB  8
#define SEQ 1024
#define ROWS (BB*SEQ)                 // 8192
#define X_ELEMS ((size_t)ROWS*H)      // 6291456
#define H3  (3*H)                     // 2304

// ---------------- scratch (static device allocations; no cudaMalloc) ------
__device__ float g_x1[ROWS*H];
__device__ float g_qkv[ROWS*H3];
__device__ float g_ctx[ROWS*H];
__device__ float g_xres[ROWS*H];
__device__ float g_x2[ROWS*H];
__device__ float g_h [ROWS*FF];
// pre-rounded + transposed weights (W^T: [N][K])
__device__ float g_wqkvT[H3*H];
__device__ float g_woT[H*H];
__device__ float g_w1T[FF*H];
__device__ float g_w2T[H*FF];
__device__ float g_bqkv[H3];

// ---------------- helpers ----------------------------------------------------
__device__ __forceinline__ float rtf32(float f) {
    unsigned u;
    asm("cvt.rna.tf32.f32 %0, %1;" : "=r"(u) : "f"(f));
    return __uint_as_float(u);
}

__device__ __forceinline__ void cp16(unsigned saddr, const void* g) {
    asm volatile("cp.async.cg.shared.global [%0], [%1], 16;\n"
                 :: "r"(saddr), "l"(g));
}

__device__ __forceinline__ void ldsm4(unsigned* r, unsigned saddr) {
    asm volatile("ldmatrix.sync.aligned.m8n8.x4.shared.b16 {%0,%1,%2,%3}, [%4];\n"
                 : "=r"(r[0]), "=r"(r[1]), "=r"(r[2]), "=r"(r[3])
                 : "r"(saddr));
}

__device__ __forceinline__ void mma8(float* d, const unsigned* a, const unsigned* b) {
    asm volatile(
        "mma.sync.aligned.m16n8k8.row.col.f32.tf32.tf32.f32 "
        "{%0,%1,%2,%3}, {%4,%5,%6,%7}, {%8,%9}, {%0,%1,%2,%3};\n"
        : "+f"(d[0]), "+f"(d[1]), "+f"(d[2]), "+f"(d[3])
        : "r"(a[0]), "r"(a[1]), "r"(a[2]), "r"(a[3]), "r"(b[0]), "r"(b[1]));
}

__device__ __forceinline__ void mma8b(float* d, const unsigned* a,
                                      unsigned b0, unsigned b1) {
    asm volatile(
        "mma.sync.aligned.m16n8k8.row.col.f32.tf32.tf32.f32 "
        "{%0,%1,%2,%3}, {%4,%5,%6,%7}, {%8,%9}, {%0,%1,%2,%3};\n"
        : "+f"(d[0]), "+f"(d[1]), "+f"(d[2]), "+f"(d[3])
        : "r"(a[0]), "r"(a[1]), "r"(a[2]), "r"(a[3]), "r"(b0), "r"(b1));
}

// ---------------- fast exp (FMA pipe) --------------------------------------
__device__ __forceinline__ float fexp(float x) {
    x = fmaxf(x, -87.0f);
    float t  = x * 1.4426950408889634f;
    float fi = rintf(t);
    float z  = t - fi;
    float p  =            1.535336188319500e-4f;
    p = fmaf(p, z, 1.339887440266574e-3f);
    p = fmaf(p, z, 9.618437357674640e-3f);
    p = fmaf(p, z, 5.550332471162809e-2f);
    p = fmaf(p, z, 2.402264791363012e-1f);
    p = fmaf(p, z, 6.931472028550421e-1f);
    p = fmaf(p, z, 1.0f);
    return __int_as_float(((int)fi + 127) << 23) * p;
}

// ---------------- transpose + tf32-round: [K][N] -> [N][K] -----------------
__global__ __launch_bounds__(256) void transpose_round(
    const float* __restrict__ s, float* __restrict__ d, int K, int N)
{
    __shared__ float t[32][33];
    int kb = blockIdx.y * 32, nb = blockIdx.x * 32;
    #pragma unroll
    for (int i = threadIdx.y; i < 32; i += 8)
        t[i][threadIdx.x] = s[(size_t)(kb + i) * N + nb + threadIdx.x];
    __syncthreads();
    #pragma unroll
    for (int i = threadIdx.y; i < 32; i += 8)
        d[(size_t)(nb + i) * K + kb + threadIdx.x] = rtf32(t[threadIdx.x][i]);
}

// ---------------- block reduce helper --------------------------------------
__device__ __forceinline__ float block_sum(float v, float* red) {
    #pragma unroll
    for (int o = 16; o; o >>= 1) v += __shfl_xor_sync(0xffffffffu, v, o);
    int w = threadIdx.x >> 5;
    if ((threadIdx.x & 31) == 0) red[w] = v;
    __syncthreads();
    float t = 0.0f;
    if (threadIdx.x < 32) {
        t = (threadIdx.x < 8) ? red[threadIdx.x] : 0.0f;
        #pragma unroll
        for (int o = 4; o; o >>= 1) t += __shfl_xor_sync(0xffffffffu, t, o);
        if (threadIdx.x == 0) red[0] = t;
    }
    __syncthreads();
    t = red[0];
    __syncthreads();
    return t;
}

// ---------------- layernorm -------------------------------------------------
template<int ROUND>
__global__ __launch_bounds__(256) void ln_kernel(
    const float* __restrict__ x, const float* __restrict__ g,
    const float* __restrict__ b, float* __restrict__ y)
{
    __shared__ float red[8];
    int row = blockIdx.x;
    const float* xr = x + (size_t)row * H;
    int t = threadIdx.x;
    float v0 = xr[t], v1 = xr[t + 256], v2 = xr[t + 512];
    float mu = block_sum(v0 + v1 + v2, red) * (1.0f / H);
    float d0 = v0 - mu, d1 = v1 - mu, d2 = v2 - mu;
    float var = block_sum(d0*d0 + d1*d1 + d2*d2, red) * (1.0f / H);
    float rs = rsqrtf(var + 1e-6f);
    float* yr = y + (size_t)row * H;
    float o0 = d0 * rs * g[t]       + b[t];
    float o1 = d1 * rs * g[t + 256] + b[t + 256];
    float o2 = d2 * rs * g[t + 512] + b[t + 512];
    if (ROUND) { o0 = rtf32(o0); o1 = rtf32(o1); o2 = rtf32(o2); }
    yr[t] = o0; yr[t + 256] = o1; yr[t + 512] = o2;
}

// ================= TF32 tensor-core GEMM (W transposed [N][K]) =============
// BM=128 BN=128 BK=32, 256 threads = 8 warps (4 m x 2 n), warp tile 32x64.
// A smem [m][k] ld=36, B smem [n][k] ld=36; fragments via ldmatrix.x4.
#define ALD 36
#define STAGE_F (128*ALD)                    // floats per stage (A or B)
#define G_SMEM (4 * STAGE_F * 4)             // 73728 B

template<int ACT, int ROUND>
__global__ __launch_bounds__(256) void gemm_tc(
    const float* __restrict__ A, const float* __restrict__ Wt,
    const float* __restrict__ bias, const float* __restrict__ res,
    float* __restrict__ C, int M, int N, int K)
{
    extern __shared__ float sm[];

    const int tid  = threadIdx.x;
    const int wid  = tid >> 5;
    const int lane = tid & 31;
    const int g    = lane >> 2;
    const int tg   = lane & 3;

    const int m0 = blockIdx.y * 128;
    const int n0 = blockIdx.x * 128;
    const int wm = (wid & 3) * 32;
    const int wn = (wid >> 2) * 64;

    unsigned sbase = (unsigned)__cvta_generic_to_shared(sm);
    const unsigned stageB = STAGE_F * 4;     // 18432 B

    // cp.async maps: A rows m (128) x 32k; B rows n (128) x 32k
    unsigned aS[4], bS[4];
    const float* aG[4];
    const float* bG[4];
    #pragma unroll
    for (int i = 0; i < 4; i++) {
        int c = tid + 256 * i;
        int r = c >> 3, cc = (c & 7) * 4;
        aS[i] = sbase + (unsigned)(r * ALD + cc) * 4;
        aG[i] = A  + (size_t)(m0 + r) * K + cc;
        bS[i] = sbase + 2 * stageB + (unsigned)(r * ALD + cc) * 4;
        bG[i] = Wt + (size_t)(n0 + r) * K + cc;
    }

    // ldmatrix per-thread offsets (bytes, relative to stage base)
    const int rsel = (lane >> 3) & 1;
    const int csel = (lane >> 4) & 1;
    unsigned aOff[2], bOff[4];
    #pragma unroll
    for (int mt = 0; mt < 2; mt++) {
        int rowA = wm + mt * 16 + (lane & 7) + rsel * 8;
        aOff[mt] = (unsigned)(rowA * ALD + csel * 4) * 4;
    }
    #pragma unroll
    for (int p = 0; p < 4; p++) {
        int rowB = wn + p * 16 + (lane & 7) + rsel * 8;
        bOff[p] = (unsigned)(rowB * ALD + csel * 4) * 4;
    }

    float d[2][8][4];
    #pragma unroll
    for (int mt = 0; mt < 2; mt++)
        #pragma unroll
        for (int nt = 0; nt < 8; nt++)
            #pragma unroll
            for (int r = 0; r < 4; r++) d[mt][nt][r] = 0.0f;

    #pragma unroll
    for (int i = 0; i < 4; i++) cp16(aS[i], aG[i]);
    #pragma unroll
    for (int i = 0; i < 4; i++) cp16(bS[i], bG[i]);
    asm volatile("cp.async.commit_group;\n");

    int s = 0;
    for (int k0 = 0; k0 < K; k0 += 32, s ^= 1) {
        if (k0 + 32 < K) {
            unsigned so = (s ^ 1) * stageB;
            #pragma unroll
            for (int i = 0; i < 4; i++) cp16(aS[i] + so, aG[i] + k0 + 32);
            #pragma unroll
            for (int i = 0; i < 4; i++) cp16(bS[i] + so, bG[i] + k0 + 32);
            asm volatile("cp.async.commit_group;\n");
            asm volatile("cp.async.wait_group 1;\n");
        } else {
            asm volatile("cp.async.wait_group 0;\n");
        }
        __syncthreads();

        const unsigned aStage = sbase + s * stageB;
        const unsigned bStage = sbase + 2 * stageB + s * stageB;
        #pragma unroll
        for (int kk = 0; kk < 4; kk++) {
            unsigned a[2][4], bb[4][4];
            ldsm4(a[0], aStage + aOff[0] + kk * 32);
            ldsm4(a[1], aStage + aOff[1] + kk * 32);
            #pragma unroll
            for (int p = 0; p < 4; p++)
                ldsm4(bb[p], bStage + bOff[p] + kk * 32);
            #pragma unroll
            for (int mt = 0; mt < 2; mt++)
                #pragma unroll
                for (int nt = 0; nt < 8; nt++) {
                    int p = nt >> 1, od = nt & 1;
                    mma8b(d[mt][nt], a[mt], bb[p][od], bb[p][od + 2]);
                }
        }
        __syncthreads();
    }

    #pragma unroll
    for (int mt = 0; mt < 2; mt++) {
        int r0 = m0 + wm + mt * 16 + g;
        #pragma unroll
        for (int nt = 0; nt < 8; nt++) {
            int c = n0 + wn + nt * 8 + 2 * tg;
            float b0 = bias[c], b1 = bias[c + 1];
            #pragma unroll
            for (int half = 0; half < 2; half++) {
                int row = r0 + half * 8;
                size_t base = (size_t)row * N + c;
                float v0 = d[mt][nt][2 * half]     + b0;
                float v1 = d[mt][nt][2 * half + 1] + b1;
                if (ACT == 1) {
                    v0 = 0.5f * v0 * (1.0f + erff(v0 * 0.70710678118654752f));
                    v1 = 0.5f * v1 * (1.0f + erff(v1 * 0.70710678118654752f));
                }
                if (res) { v0 += res[base]; v1 += res[base + 1]; }
                if (ROUND) { v0 = rtf32(v0); v1 = rtf32(v1); }
                float2 o; o.x = v0; o.y = v1;
                *(float2*)(C + base) = o;
            }
        }
    }
}

// ================= tensor-core fused attention ==============================
// QKV packed: row stride H3; q at col h*DH, k at H + h*DH, v at 2H + h*DH.
#define KV_LD 68
#define SS_LD 1028
#define ATT_SMEM ((32*KV_LD + 2*128*KV_LD + 32*SS_LD) * 4)   // 210048 B

__device__ __forceinline__ void load_kv(unsigned skv, const float* gp,
                                        int chunk, int buf, int tid) {
    #pragma unroll
    for (int i = 0; i < 8; i++) {
        int idx = tid + 256 * i;
        int r = idx >> 4, c = (idx & 15) * 4;
        cp16(skv + (unsigned)(buf * 128 * KV_LD + r * KV_LD + c) * 4,
             gp + (size_t)(chunk * 128 + r) * H3 + c);
    }
}

__global__ __launch_bounds__(256) void attn_tc(
    const float* __restrict__ QKV, float* __restrict__ Wout,
    float* __restrict__ Ctx)
{
    extern __shared__ float sm[];
    float* sQ  = sm;                          // [32][68]
    float* sKV = sQ + 32 * KV_LD;             // [2][128][68]
    float* sS  = sKV + 2 * 128 * KV_LD;       // [32][1028]

    const int tid  = threadIdx.x;
    const int wid  = tid >> 5;
    const int lane = tid & 31;
    const int g    = lane >> 2;
    const int tg   = lane & 3;
    const int q0   = blockIdx.x * 32;
    const int h    = blockIdx.y;
    const int b    = blockIdx.z;
    const float scale = 0.03608439182435161f;   // 1/sqrt(768)

    const size_t rowb = (size_t)b * SEQ * H3;
    const float* Qp = QKV + rowb + (size_t)q0 * H3 + h * DH;
    const float* Kp = QKV + rowb + H  + h * DH;
    const float* Vp = QKV + rowb + 2 * H + h * DH;

    unsigned sQb  = (unsigned)__cvta_generic_to_shared(sQ);
    unsigned sKVb = (unsigned)__cvta_generic_to_shared(sKV);

    #pragma unroll
    for (int i = 0; i < 2; i++) {
        int idx = tid + 256 * i;
        int r = idx >> 4, c = (idx & 15) * 4;
        cp16(sQb + (unsigned)(r * KV_LD + c) * 4, Qp + (size_t)r * H3 + c);
    }
    load_kv(sKVb, Kp, 0, 0, tid);
    asm volatile("cp.async.commit_group;\n");
    load_kv(sKVb, Kp, 1, 1, tid);
    asm volatile("cp.async.commit_group;\n");
    asm volatile("cp.async.wait_group 1;\n");
    __syncthreads();

    unsigned qf[2][8][4];
    #pragma unroll
    for (int ks = 0; ks < 8; ks++)
        #pragma unroll
        for (int mt = 0; mt < 2; mt++) {
            const float* Qr = sQ + (g + mt * 16) * KV_LD + ks * 8 + tg;
            qf[mt][ks][0] = __float_as_uint(Qr[0]);
            qf[mt][ks][1] = __float_as_uint(Qr[8 * KV_LD]);
            qf[mt][ks][2] = __float_as_uint(Qr[4]);
            qf[mt][ks][3] = __float_as_uint(Qr[8 * KV_LD + 4]);
        }

    // ---- phase 1: scores ----
    for (int jt = 0; jt < 8; jt++) {
        const float* Kb = sKV + (jt & 1) * 128 * KV_LD;
        float acc[2][2][4];
        #pragma unroll
        for (int mt = 0; mt < 2; mt++)
            #pragma unroll
            for (int nt = 0; nt < 2; nt++)
                #pragma unroll
                for (int r = 0; r < 4; r++) acc[mt][nt][r] = 0.0f;
        #pragma unroll
        for (int ks = 0; ks < 8; ks++) {
            unsigned bf[2][2];
            #pragma unroll
            for (int nt = 0; nt < 2; nt++) {
                const float* Kr = Kb + (wid * 16 + nt * 8 + g) * KV_LD + ks * 8 + tg;
                bf[nt][0] = __float_as_uint(Kr[0]);
                bf[nt][1] = __float_as_uint(Kr[4]);
            }
            #pragma unroll
            for (int mt = 0; mt < 2; mt++)
                #pragma unroll
                for (int nt = 0; nt < 2; nt++)
                    mma8(acc[mt][nt], qf[mt][ks], bf[nt]);
        }
        #pragma unroll
        for (int mt = 0; mt < 2; mt++)
            #pragma unroll
            for (int nt = 0; nt < 2; nt++) {
                int col = jt * 128 + wid * 16 + nt * 8 + 2 * tg;
                int r1 = g + mt * 16;
                float2 o0; o0.x = acc[mt][nt][0] * scale; o0.y = acc[mt][nt][1] * scale;
                float2 o1; o1.x = acc[mt][nt][2] * scale; o1.y = acc[mt][nt][3] * scale;
                *(float2*)&sS[r1 * SS_LD + col]       = o0;
                *(float2*)&sS[(r1 + 8) * SS_LD + col] = o1;
            }
        __syncthreads();
        if (jt < 6) {
            load_kv(sKVb, Kp, jt + 2, jt & 1, tid);
            asm volatile("cp.async.commit_group;\n");
        }
        if (jt < 7) {
            if (jt < 6) asm volatile("cp.async.wait_group 1;\n");
            else        asm volatile("cp.async.wait_group 0;\n");
            __syncthreads();
        }
    }

    load_kv(sKVb, Vp, 0, 0, tid);
    asm volatile("cp.async.commit_group;\n");

    // ---- phase 2: softmax ----
    {
        for (int rr = 0; rr < 4; rr++) {
            float* srow = &sS[(wid + rr * 8) * SS_LD];
            float m = -1e30f;
            for (int t = lane; t < SEQ; t += 32) m = fmaxf(m, srow[t]);
            #pragma unroll
            for (int o = 16; o; o >>= 1) m = fmaxf(m, __shfl_xor_sync(0xffffffffu, m, o));
            float ssum = 0.0f;
            for (int t = lane; t < SEQ; t += 32) {
                float e = fexp(srow[t] - m);
                srow[t] = e;
                ssum += e;
            }
            #pragma unroll
            for (int o = 16; o; o >>= 1) ssum += __shfl_xor_sync(0xffffffffu, ssum, o);
            float inv = 1.0f / ssum;
            for (int t = lane; t < SEQ; t += 32) srow[t] *= inv;
        }
    }
    __syncthreads();

    // ---- phase 3: write weights (f32) + round P in smem to tf32 ----
    {
        float* Wrow = Wout + ((size_t)(b * NH + h) * SEQ + q0) * SEQ;
        for (int s = tid; s < 32 * 256; s += 256) {
            int r = s >> 8, c4 = (s & 255) * 4;
            float4 v = *(const float4*)&sS[r * SS_LD + c4];
            *(float4*)(Wrow + (size_t)r * SEQ + c4) = v;
            v.x = rtf32(v.x); v.y = rtf32(v.y); v.z = rtf32(v.z); v.w = rtf32(v.w);
            *(float4*)&sS[r * SS_LD + c4] = v;
        }
    }
    __syncthreads();

    load_kv(sKVb, Vp, 1, 1, tid);
    asm volatile("cp.async.commit_group;\n");
    asm volatile("cp.async.wait_group 1;\n");
    __syncthreads();

    // ---- phase 4: ctx = P @ V ----
    float acc2[2][4];
    #pragma unroll
    for (int mt = 0; mt < 2; mt++)
        #pragma unroll
        for (int r = 0; r < 4; r++) acc2[mt][r] = 0.0f;

    for (int kt = 0; kt < 8; kt++) {
        const float* Vb = sKV + (kt & 1) * 128 * KV_LD;
        #pragma unroll 4
        for (int ks = 0; ks < 16; ks++) {
            int kcol = kt * 128 + ks * 8;
            unsigned bf[2];
            bf[0] = __float_as_uint(Vb[(ks * 8 + tg)     * KV_LD + wid * 8 + g]);
            bf[1] = __float_as_uint(Vb[(ks * 8 + tg + 4) * KV_LD + wid * 8 + g]);
            #pragma unroll
            for (int mt = 0; mt < 2; mt++) {
                unsigned af[4];
                const float* Pr = sS + (g + mt * 16) * SS_LD + kcol + tg;
                af[0] = __float_as_uint(Pr[0]);
                af[1] = __float_as_uint(Pr[8 * SS_LD]);
                af[2] = __float_as_uint(Pr[4]);
                af[3] = __float_as_uint(Pr[8 * SS_LD + 4]);
                mma8(acc2[mt], af, bf);
            }
        }
        __syncthreads();
        if (kt < 6) {
            load_kv(sKVb, Vp, kt + 2, kt & 1, tid);
            asm volatile("cp.async.commit_group;\n");
        }
        if (kt < 7) {
            if (kt < 6) asm volatile("cp.async.wait_group 1;\n");
            else        asm volatile("cp.async.wait_group 0;\n");
            __syncthreads();
        }
    }

    #pragma unroll
    for (int mt = 0; mt < 2; mt++)
        #pragma unroll
        for (int half = 0; half < 2; half++) {
            int row = q0 + g + mt * 16 + half * 8;
            int col = h * DH + wid * 8 + 2 * tg;
            float2 o;
            o.x = rtf32(acc2[mt][2 * half]);
            o.y = rtf32(acc2[mt][2 * half + 1]);
            *(float2*)(Ctx + ((size_t)b * SEQ + row) * H + col) = o;
        }
}

// ---------------- launch ---------------------------------------------------
extern "C" void kernel_launch(void* const* d_in, const int* in_sizes, int n_in,
                              void* d_out, int out_size)
{
    const float* x   = (const float*)d_in[0];
    const float* wq  = (const float*)d_in[1];
    const float* bq  = (const float*)d_in[2];
    const float* wk  = (const float*)d_in[3];
    const float* bk  = (const float*)d_in[4];
    const float* wv  = (const float*)d_in[5];
    const float* bv  = (const float*)d_in[6];
    const float* wo  = (const float*)d_in[7];
    const float* bo  = (const float*)d_in[8];
    const float* w1  = (const float*)d_in[9];
    const float* b1  = (const float*)d_in[10];
    const float* w2  = (const float*)d_in[11];
    const float* b2  = (const float*)d_in[12];
    const float* g1  = (const float*)d_in[13];
    const float* be1 = (const float*)d_in[14];
    const float* g2  = (const float*)d_in[15];
    const float* be2 = (const float*)d_in[16];

    float* out_x = (float*)d_out;
    float* out_w = (float*)d_out + X_ELEMS;

    float *px1, *pqkv, *pctx, *pxres, *px2, *ph;
    float *pwqkvT, *pwoT, *pw1T, *pw2T, *pbqkv;
    cudaGetSymbolAddress((void**)&px1,    g_x1);
    cudaGetSymbolAddress((void**)&pqkv,   g_qkv);
    cudaGetSymbolAddress((void**)&pctx,   g_ctx);
    cudaGetSymbolAddress((void**)&pxres,  g_xres);
    cudaGetSymbolAddress((void**)&px2,    g_x2);
    cudaGetSymbolAddress((void**)&ph,     g_h);
    cudaGetSymbolAddress((void**)&pwqkvT, g_wqkvT);
    cudaGetSymbolAddress((void**)&pwoT,   g_woT);
    cudaGetSymbolAddress((void**)&pw1T,   g_w1T);
    cudaGetSymbolAddress((void**)&pw2T,   g_w2T);
    cudaGetSymbolAddress((void**)&pbqkv,  g_bqkv);

    cudaFuncSetAttribute(attn_tc,
        cudaFuncAttributeMaxDynamicSharedMemorySize, ATT_SMEM);
    cudaFuncSetAttribute(gemm_tc<0,0>,
        cudaFuncAttributeMaxDynamicSharedMemorySize, G_SMEM);
    cudaFuncSetAttribute(gemm_tc<0,1>,
        cudaFuncAttributeMaxDynamicSharedMemorySize, G_SMEM);
    cudaFuncSetAttribute(gemm_tc<1,1>,
        cudaFuncAttributeMaxDynamicSharedMemorySize, G_SMEM);

    // 0) transpose + round weights; concat qkv weights/biases
    dim3 tb(32, 8);
    transpose_round<<<dim3(H/32,  H/32),  tb>>>(wq, pwqkvT,             H, H);
    transpose_round<<<dim3(H/32,  H/32),  tb>>>(wk, pwqkvT + H*H,       H, H);
    transpose_round<<<dim3(H/32,  H/32),  tb>>>(wv, pwqkvT + 2*H*H,     H, H);
    transpose_round<<<dim3(H/32,  H/32),  tb>>>(wo, pwoT,               H, H);
    transpose_round<<<dim3(FF/32, H/32),  tb>>>(w1, pw1T,               H, FF);
    transpose_round<<<dim3(H/32,  FF/32), tb>>>(w2, pw2T,               FF, H);
    cudaMemcpyAsync(pbqkv,         bq, H*sizeof(float), cudaMemcpyDeviceToDevice);
    cudaMemcpyAsync(pbqkv + H,     bk, H*sizeof(float), cudaMemcpyDeviceToDevice);
    cudaMemcpyAsync(pbqkv + 2*H,   bv, H*sizeof(float), cudaMemcpyDeviceToDevice);

    // 1) LN1 (rounded)
    ln_kernel<1><<<ROWS, 256>>>(x, g1, be1, px1);

    // 2) fused QKV projection (rounded out)
    gemm_tc<0,1><<<dim3(H3/128, ROWS/128), 256, G_SMEM>>>(
        px1, pwqkvT, pbqkv, nullptr, pqkv, ROWS, H3, H);

    // 3) attention
    attn_tc<<<dim3(SEQ/32, NH, BB), 256, ATT_SMEM>>>(pqkv, out_w, pctx);

    // 4) output projection + residual(x)
    gemm_tc<0,0><<<dim3(H/128, ROWS/128), 256, G_SMEM>>>(
        pctx, pwoT, bo, x, pxres, ROWS, H, H);

    // 5) LN2 (rounded)
    ln_kernel<1><<<ROWS, 256>>>(pxres, g2, be2, px2);

    // 6) MLP
    gemm_tc<1,1><<<dim3(FF/128, ROWS/128), 256, G_SMEM>>>(
        px2, pw1T, b1, nullptr, ph, ROWS, FF, H);
    gemm_tc<0,0><<<dim3(H/128, ROWS/128), 256, G_SMEM>>>(
        ph, pw2T, b2, pxres, out_x, ROWS, H, FF);
}

// round 6
// speedup vs baseline: 3.3856x; 1.0011x over previous
#include <cuda_runtime.h>
#include <math.h>

#define H   768
#define NH  12
#define DH  64
#define FF  3072
#define BB  8
#define SEQ 1024
#define ROWS (BB*SEQ)                 // 8192
#define X_ELEMS ((size_t)ROWS*H)      // 6291456
#define H3  (3*H)                     // 2304

// ---------------- scratch (static device allocations; no cudaMalloc) ------
__device__ float g_x1[ROWS*H];
__device__ float g_qkv[ROWS*H3];
__device__ float g_ctx[ROWS*H];
__device__ float g_xres[ROWS*H];
__device__ float g_x2[ROWS*H];
__device__ float g_h [ROWS*FF];
// pre-rounded + transposed weights (W^T: [N][K])
__device__ float g_wqkvT[H3*H];
__device__ float g_woT[H*H];
__device__ float g_w1T[FF*H];
__device__ float g_w2T[H*FF];
__device__ float g_bqkv[H3];

// ---------------- helpers ----------------------------------------------------
__device__ __forceinline__ float rtf32(float f) {
    unsigned u;
    asm("cvt.rna.tf32.f32 %0, %1;" : "=r"(u) : "f"(f));
    return __uint_as_float(u);
}

__device__ __forceinline__ void cp16(unsigned saddr, const void* g) {
    asm volatile("cp.async.cg.shared.global [%0], [%1], 16;\n"
                 :: "r"(saddr), "l"(g));
}

__device__ __forceinline__ void ldsm4(unsigned* r, unsigned saddr) {
    asm volatile("ldmatrix.sync.aligned.m8n8.x4.shared.b16 {%0,%1,%2,%3}, [%4];\n"
                 : "=r"(r[0]), "=r"(r[1]), "=r"(r[2]), "=r"(r[3])
                 : "r"(saddr));
}

__device__ __forceinline__ void mma8(float* d, const unsigned* a, const unsigned* b) {
    asm volatile(
        "mma.sync.aligned.m16n8k8.row.col.f32.tf32.tf32.f32 "
        "{%0,%1,%2,%3}, {%4,%5,%6,%7}, {%8,%9}, {%0,%1,%2,%3};\n"
        : "+f"(d[0]), "+f"(d[1]), "+f"(d[2]), "+f"(d[3])
        : "r"(a[0]), "r"(a[1]), "r"(a[2]), "r"(a[3]), "r"(b[0]), "r"(b[1]));
}

__device__ __forceinline__ void mma8b(float* d, const unsigned* a,
                                      unsigned b0, unsigned b1) {
    asm volatile(
        "mma.sync.aligned.m16n8k8.row.col.f32.tf32.tf32.f32 "
        "{%0,%1,%2,%3}, {%4,%5,%6,%7}, {%8,%9}, {%0,%1,%2,%3};\n"
        : "+f"(d[0]), "+f"(d[1]), "+f"(d[2]), "+f"(d[3])
        : "r"(a[0]), "r"(a[1]), "r"(a[2]), "r"(a[3]), "r"(b0), "r"(b1));
}

// ---------------- fast exp (FMA pipe) --------------------------------------
__device__ __forceinline__ float fexp(float x) {
    x = fmaxf(x, -87.0f);
    float t  = x * 1.4426950408889634f;
    float fi = rintf(t);
    float z  = t - fi;
    float p  =            1.535336188319500e-4f;
    p = fmaf(p, z, 1.339887440266574e-3f);
    p = fmaf(p, z, 9.618437357674640e-3f);
    p = fmaf(p, z, 5.550332471162809e-2f);
    p = fmaf(p, z, 2.402264791363012e-1f);
    p = fmaf(p, z, 6.931472028550421e-1f);
    p = fmaf(p, z, 1.0f);
    return __int_as_float(((int)fi + 127) << 23) * p;
}

// ---------------- transpose + tf32-round: [K][N] -> [N][K] -----------------
__global__ __launch_bounds__(256) void transpose_round(
    const float* __restrict__ s, float* __restrict__ d, int K, int N)
{
    __shared__ float t[32][33];
    int kb = blockIdx.y * 32, nb = blockIdx.x * 32;
    #pragma unroll
    for (int i = threadIdx.y; i < 32; i += 8)
        t[i][threadIdx.x] = s[(size_t)(kb + i) * N + nb + threadIdx.x];
    __syncthreads();
    #pragma unroll
    for (int i = threadIdx.y; i < 32; i += 8)
        d[(size_t)(nb + i) * K + kb + threadIdx.x] = rtf32(t[threadIdx.x][i]);
}

// ---------------- block reduce helper --------------------------------------
__device__ __forceinline__ float block_sum(float v, float* red) {
    #pragma unroll
    for (int o = 16; o; o >>= 1) v += __shfl_xor_sync(0xffffffffu, v, o);
    int w = threadIdx.x >> 5;
    if ((threadIdx.x & 31) == 0) red[w] = v;
    __syncthreads();
    float t = 0.0f;
    if (threadIdx.x < 32) {
        t = (threadIdx.x < 8) ? red[threadIdx.x] : 0.0f;
        #pragma unroll
        for (int o = 4; o; o >>= 1) t += __shfl_xor_sync(0xffffffffu, t, o);
        if (threadIdx.x == 0) red[0] = t;
    }
    __syncthreads();
    t = red[0];
    __syncthreads();
    return t;
}

// ---------------- layernorm -------------------------------------------------
template<int ROUND>
__global__ __launch_bounds__(256) void ln_kernel(
    const float* __restrict__ x, const float* __restrict__ g,
    const float* __restrict__ b, float* __restrict__ y)
{
    __shared__ float red[8];
    int row = blockIdx.x;
    const float* xr = x + (size_t)row * H;
    int t = threadIdx.x;
    float v0 = xr[t], v1 = xr[t + 256], v2 = xr[t + 512];
    float mu = block_sum(v0 + v1 + v2, red) * (1.0f / H);
    float d0 = v0 - mu, d1 = v1 - mu, d2 = v2 - mu;
    float var = block_sum(d0*d0 + d1*d1 + d2*d2, red) * (1.0f / H);
    float rs = rsqrtf(var + 1e-6f);
    float* yr = y + (size_t)row * H;
    float o0 = d0 * rs * g[t]       + b[t];
    float o1 = d1 * rs * g[t + 256] + b[t + 256];
    float o2 = d2 * rs * g[t + 512] + b[t + 512];
    if (ROUND) { o0 = rtf32(o0); o1 = rtf32(o1); o2 = rtf32(o2); }
    yr[t] = o0; yr[t + 256] = o1; yr[t + 512] = o2;
}

// ================= TF32 tensor-core GEMM (W transposed [N][K]) =============
// BM=128 BN=128 BK=32, 256 threads = 8 warps (4 m x 2 n), warp tile 32x64.
// 3-stage cp.async ring, copies issued 2 iters ahead, ONE barrier per iter.
#define ALD 36
#define STAGE_F (128*ALD)                    // floats per operand stage
#define STAGE_B (STAGE_F*4)                  // 18432 bytes
#define G_SMEM  (6*STAGE_B)                  // 110592 B (A x3 | B x3)

template<int ACT, int ROUND>
__global__ __launch_bounds__(256, 2) void gemm_tc(
    const float* __restrict__ A, const float* __restrict__ Wt,
    const float* __restrict__ bias, const float* __restrict__ res,
    float* __restrict__ C, int M, int N, int K)
{
    extern __shared__ float sm[];

    const int tid  = threadIdx.x;
    const int wid  = tid >> 5;
    const int lane = tid & 31;
    const int g    = lane >> 2;
    const int tg   = lane & 3;

    const int m0 = blockIdx.y * 128;
    const int n0 = blockIdx.x * 128;
    const int wm = (wid & 3) * 32;
    const int wn = (wid >> 2) * 64;

    unsigned sbase = (unsigned)__cvta_generic_to_shared(sm);

    // cp.async maps: A rows m (128) x 32k; B rows n (128) x 32k
    unsigned aS[4], bS[4];
    const float* aG[4];
    const float* bG[4];
    #pragma unroll
    for (int i = 0; i < 4; i++) {
        int c = tid + 256 * i;
        int r = c >> 3, cc = (c & 7) * 4;
        aS[i] = sbase + (unsigned)(r * ALD + cc) * 4;
        aG[i] = A  + (size_t)(m0 + r) * K + cc;
        bS[i] = sbase + 3 * STAGE_B + (unsigned)(r * ALD + cc) * 4;
        bG[i] = Wt + (size_t)(n0 + r) * K + cc;
    }

    // ldmatrix per-thread offsets (bytes, relative to stage base)
    const int rsel = (lane >> 3) & 1;
    const int csel = (lane >> 4) & 1;
    unsigned aOff[2], bOff[4];
    #pragma unroll
    for (int mt = 0; mt < 2; mt++) {
        int rowA = wm + mt * 16 + (lane & 7) + rsel * 8;
        aOff[mt] = (unsigned)(rowA * ALD + csel * 4) * 4;
    }
    #pragma unroll
    for (int p = 0; p < 4; p++) {
        int rowB = wn + p * 16 + (lane & 7) + rsel * 8;
        bOff[p] = (unsigned)(rowB * ALD + csel * 4) * 4;
    }

    float d[2][8][4];
    #pragma unroll
    for (int mt = 0; mt < 2; mt++)
        #pragma unroll
        for (int nt = 0; nt < 8; nt++)
            #pragma unroll
            for (int r = 0; r < 4; r++) d[mt][nt][r] = 0.0f;

    const int KIT = K >> 5;

    // fill stage s with K-chunk it
    auto fill = [&](int it, int s) {
        unsigned so = (unsigned)s * STAGE_B;
        int k0 = it * 32;
        #pragma unroll
        for (int i = 0; i < 4; i++) cp16(aS[i] + so, aG[i] + k0);
        #pragma unroll
        for (int i = 0; i < 4; i++) cp16(bS[i] + so, bG[i] + k0);
    };

    fill(0, 0); asm volatile("cp.async.commit_group;\n");
    fill(1, 1); asm volatile("cp.async.commit_group;\n");

    int s = 0;
    for (int it = 0; it < KIT; it++) {
        // stage s = it % 3; copies for it were issued 2 iters ago
        asm volatile("cp.async.wait_group 1;\n");
        __syncthreads();
        // refill stage (it+2)%3 == (it-1)%3 (finished computing last iter,
        // and the barrier above made that globally visible)
        if (it + 2 < KIT) {
            int s2 = s + 2; if (s2 >= 3) s2 -= 3;
            fill(it + 2, s2);
        }
        asm volatile("cp.async.commit_group;\n");

        const unsigned aStage = sbase + (unsigned)s * STAGE_B;
        const unsigned bStage = sbase + 3 * STAGE_B + (unsigned)s * STAGE_B;
        #pragma unroll
        for (int kk = 0; kk < 4; kk++) {
            unsigned a[2][4], bb[4][4];
            ldsm4(a[0], aStage + aOff[0] + kk * 32);
            ldsm4(a[1], aStage + aOff[1] + kk * 32);
            #pragma unroll
            for (int p = 0; p < 4; p++)
                ldsm4(bb[p], bStage + bOff[p] + kk * 32);
            #pragma unroll
            for (int mt = 0; mt < 2; mt++)
                #pragma unroll
                for (int nt = 0; nt < 8; nt++) {
                    int p = nt >> 1, od = nt & 1;
                    mma8b(d[mt][nt], a[mt], bb[p][od], bb[p][od + 2]);
                }
        }
        if (++s >= 3) s = 0;
    }

    #pragma unroll
    for (int mt = 0; mt < 2; mt++) {
        int r0 = m0 + wm + mt * 16 + g;
        #pragma unroll
        for (int nt = 0; nt < 8; nt++) {
            int c = n0 + wn + nt * 8 + 2 * tg;
            float b0 = bias[c], b1 = bias[c + 1];
            #pragma unroll
            for (int half = 0; half < 2; half++) {
                int row = r0 + half * 8;
                size_t base = (size_t)row * N + c;
                float v0 = d[mt][nt][2 * half]     + b0;
                float v1 = d[mt][nt][2 * half + 1] + b1;
                if (ACT == 1) {
                    v0 = 0.5f * v0 * (1.0f + erff(v0 * 0.70710678118654752f));
                    v1 = 0.5f * v1 * (1.0f + erff(v1 * 0.70710678118654752f));
                }
                if (res) { v0 += res[base]; v1 += res[base + 1]; }
                if (ROUND) { v0 = rtf32(v0); v1 = rtf32(v1); }
                float2 o; o.x = v0; o.y = v1;
                *(float2*)(C + base) = o;
            }
        }
    }
}

// ================= tensor-core fused attention ==============================
// QKV packed: row stride H3; q at col h*DH, k at H + h*DH, v at 2H + h*DH.
#define KV_LD 68
#define SS_LD 1028
#define ATT_SMEM ((32*KV_LD + 2*128*KV_LD + 32*SS_LD) * 4)   // 210048 B

__device__ __forceinline__ void load_kv(unsigned skv, const float* gp,
                                        int chunk, int buf, int tid) {
    #pragma unroll
    for (int i = 0; i < 8; i++) {
        int idx = tid + 256 * i;
        int r = idx >> 4, c = (idx & 15) * 4;
        cp16(skv + (unsigned)(buf * 128 * KV_LD + r * KV_LD + c) * 4,
             gp + (size_t)(chunk * 128 + r) * H3 + c);
    }
}

__global__ __launch_bounds__(256) void attn_tc(
    const float* __restrict__ QKV, float* __restrict__ Wout,
    float* __restrict__ Ctx)
{
    extern __shared__ float sm[];
    float* sQ  = sm;
    float* sKV = sQ + 32 * KV_LD;
    float* sS  = sKV + 2 * 128 * KV_LD;

    const int tid  = threadIdx.x;
    const int wid  = tid >> 5;
    const int lane = tid & 31;
    const int g    = lane >> 2;
    const int tg   = lane & 3;
    const int q0   = blockIdx.x * 32;
    const int h    = blockIdx.y;
    const int b    = blockIdx.z;
    const float scale = 0.03608439182435161f;   // 1/sqrt(768)

    const size_t rowb = (size_t)b * SEQ * H3;
    const float* Qp = QKV + rowb + (size_t)q0 * H3 + h * DH;
    const float* Kp = QKV + rowb + H  + h * DH;
    const float* Vp = QKV + rowb + 2 * H + h * DH;

    unsigned sQb  = (unsigned)__cvta_generic_to_shared(sQ);
    unsigned sKVb = (unsigned)__cvta_generic_to_shared(sKV);

    #pragma unroll
    for (int i = 0; i < 2; i++) {
        int idx = tid + 256 * i;
        int r = idx >> 4, c = (idx & 15) * 4;
        cp16(sQb + (unsigned)(r * KV_LD + c) * 4, Qp + (size_t)r * H3 + c);
    }
    load_kv(sKVb, Kp, 0, 0, tid);
    asm volatile("cp.async.commit_group;\n");
    load_kv(sKVb, Kp, 1, 1, tid);
    asm volatile("cp.async.commit_group;\n");
    asm volatile("cp.async.wait_group 1;\n");
    __syncthreads();

    unsigned qf[2][8][4];
    #pragma unroll
    for (int ks = 0; ks < 8; ks++)
        #pragma unroll
        for (int mt = 0; mt < 2; mt++) {
            const float* Qr = sQ + (g + mt * 16) * KV_LD + ks * 8 + tg;
            qf[mt][ks][0] = __float_as_uint(Qr[0]);
            qf[mt][ks][1] = __float_as_uint(Qr[8 * KV_LD]);
            qf[mt][ks][2] = __float_as_uint(Qr[4]);
            qf[mt][ks][3] = __float_as_uint(Qr[8 * KV_LD + 4]);
        }

    // ---- phase 1: scores ----
    for (int jt = 0; jt < 8; jt++) {
        const float* Kb = sKV + (jt & 1) * 128 * KV_LD;
        float acc[2][2][4];
        #pragma unroll
        for (int mt = 0; mt < 2; mt++)
            #pragma unroll
            for (int nt = 0; nt < 2; nt++)
                #pragma unroll
                for (int r = 0; r < 4; r++) acc[mt][nt][r] = 0.0f;
        #pragma unroll
        for (int ks = 0; ks < 8; ks++) {
            unsigned bf[2][2];
            #pragma unroll
            for (int nt = 0; nt < 2; nt++) {
                const float* Kr = Kb + (wid * 16 + nt * 8 + g) * KV_LD + ks * 8 + tg;
                bf[nt][0] = __float_as_uint(Kr[0]);
                bf[nt][1] = __float_as_uint(Kr[4]);
            }
            #pragma unroll
            for (int mt = 0; mt < 2; mt++)
                #pragma unroll
                for (int nt = 0; nt < 2; nt++)
                    mma8(acc[mt][nt], qf[mt][ks], bf[nt]);
        }
        #pragma unroll
        for (int mt = 0; mt < 2; mt++)
            #pragma unroll
            for (int nt = 0; nt < 2; nt++) {
                int col = jt * 128 + wid * 16 + nt * 8 + 2 * tg;
                int r1 = g + mt * 16;
                float2 o0; o0.x = acc[mt][nt][0] * scale; o0.y = acc[mt][nt][1] * scale;
                float2 o1; o1.x = acc[mt][nt][2] * scale; o1.y = acc[mt][nt][3] * scale;
                *(float2*)&sS[r1 * SS_LD + col]       = o0;
                *(float2*)&sS[(r1 + 8) * SS_LD + col] = o1;
            }
        __syncthreads();
        if (jt < 6) {
            load_kv(sKVb, Kp, jt + 2, jt & 1, tid);
            asm volatile("cp.async.commit_group;\n");
        }
        if (jt < 7) {
            if (jt < 6) asm volatile("cp.async.wait_group 1;\n");
            else        asm volatile("cp.async.wait_group 0;\n");
            __syncthreads();
        }
    }

    load_kv(sKVb, Vp, 0, 0, tid);
    asm volatile("cp.async.commit_group;\n");

    // ---- phase 2: softmax ----
    {
        for (int rr = 0; rr < 4; rr++) {
            float* srow = &sS[(wid + rr * 8) * SS_LD];
            float m = -1e30f;
            for (int t = lane; t < SEQ; t += 32) m = fmaxf(m, srow[t]);
            #pragma unroll
            for (int o = 16; o; o >>= 1) m = fmaxf(m, __shfl_xor_sync(0xffffffffu, m, o));
            float ssum = 0.0f;
            for (int t = lane; t < SEQ; t += 32) {
                float e = fexp(srow[t] - m);
                srow[t] = e;
                ssum += e;
            }
            #pragma unroll
            for (int o = 16; o; o >>= 1) ssum += __shfl_xor_sync(0xffffffffu, ssum, o);
            float inv = 1.0f / ssum;
            for (int t = lane; t < SEQ; t += 32) srow[t] *= inv;
        }
    }
    __syncthreads();

    // ---- phase 3: write weights (f32) + round P in smem to tf32 ----
    {
        float* Wrow = Wout + ((size_t)(b * NH + h) * SEQ + q0) * SEQ;
        for (int s = tid; s < 32 * 256; s += 256) {
            int r = s >> 8, c4 = (s & 255) * 4;
            float4 v = *(const float4*)&sS[r * SS_LD + c4];
            *(float4*)(Wrow + (size_t)r * SEQ + c4) = v;
            v.x = rtf32(v.x); v.y = rtf32(v.y); v.z = rtf32(v.z); v.w = rtf32(v.w);
            *(float4*)&sS[r * SS_LD + c4] = v;
        }
    }
    __syncthreads();

    load_kv(sKVb, Vp, 1, 1, tid);
    asm volatile("cp.async.commit_group;\n");
    asm volatile("cp.async.wait_group 1;\n");
    __syncthreads();

    // ---- phase 4: ctx = P @ V ----
    float acc2[2][4];
    #pragma unroll
    for (int mt = 0; mt < 2; mt++)
        #pragma unroll
        for (int r = 0; r < 4; r++) acc2[mt][r] = 0.0f;

    for (int kt = 0; kt < 8; kt++) {
        const float* Vb = sKV + (kt & 1) * 128 * KV_LD;
        #pragma unroll 4
        for (int ks = 0; ks < 16; ks++) {
            int kcol = kt * 128 + ks * 8;
            unsigned bf[2];
            bf[0] = __float_as_uint(Vb[(ks * 8 + tg)     * KV_LD + wid * 8 + g]);
            bf[1] = __float_as_uint(Vb[(ks * 8 + tg + 4) * KV_LD + wid * 8 + g]);
            #pragma unroll
            for (int mt = 0; mt < 2; mt++) {
                unsigned af[4];
                const float* Pr = sS + (g + mt * 16) * SS_LD + kcol + tg;
                af[0] = __float_as_uint(Pr[0]);
                af[1] = __float_as_uint(Pr[8 * SS_LD]);
                af[2] = __float_as_uint(Pr[4]);
                af[3] = __float_as_uint(Pr[8 * SS_LD + 4]);
                mma8(acc2[mt], af, bf);
            }
        }
        __syncthreads();
        if (kt < 6) {
            load_kv(sKVb, Vp, kt + 2, kt & 1, tid);
            asm volatile("cp.async.commit_group;\n");
        }
        if (kt < 7) {
            if (kt < 6) asm volatile("cp.async.wait_group 1;\n");
            else        asm volatile("cp.async.wait_group 0;\n");
            __syncthreads();
        }
    }

    #pragma unroll
    for (int mt = 0; mt < 2; mt++)
        #pragma unroll
        for (int half = 0; half < 2; half++) {
            int row = q0 + g + mt * 16 + half * 8;
            int col = h * DH + wid * 8 + 2 * tg;
            float2 o;
            o.x = rtf32(acc2[mt][2 * half]);
            o.y = rtf32(acc2[mt][2 * half + 1]);
            *(float2*)(Ctx + ((size_t)b * SEQ + row) * H + col) = o;
        }
}

// ---------------- launch ---------------------------------------------------
extern "C" void kernel_launch(void* const* d_in, const int* in_sizes, int n_in,
                              void* d_out, int out_size)
{
    const float* x   = (const float*)d_in[0];
    const float* wq  = (const float*)d_in[1];
    const float* bq  = (const float*)d_in[2];
    const float* wk  = (const float*)d_in[3];
    const float* bk  = (const float*)d_in[4];
    const float* wv  = (const float*)d_in[5];
    const float* bv  = (const float*)d_in[6];
    const float* wo  = (const float*)d_in[7];
    const float* bo  = (const float*)d_in[8];
    const float* w1  = (const float*)d_in[9];
    const float* b1  = (const float*)d_in[10];
    const float* w2  = (const float*)d_in[11];
    const float* b2  = (const float*)d_in[12];
    const float* g1  = (const float*)d_in[13];
    const float* be1 = (const float*)d_in[14];
    const float* g2  = (const float*)d_in[15];
    const float* be2 = (const float*)d_in[16];

    float* out_x = (float*)d_out;
    float* out_w = (float*)d_out + X_ELEMS;

    float *px1, *pqkv, *pctx, *pxres, *px2, *ph;
    float *pwqkvT, *pwoT, *pw1T, *pw2T, *pbqkv;
    cudaGetSymbolAddress((void**)&px1,    g_x1);
    cudaGetSymbolAddress((void**)&pqkv,   g_qkv);
    cudaGetSymbolAddress((void**)&pctx,   g_ctx);
    cudaGetSymbolAddress((void**)&pxres,  g_xres);
    cudaGetSymbolAddress((void**)&px2,    g_x2);
    cudaGetSymbolAddress((void**)&ph,     g_h);
    cudaGetSymbolAddress((void**)&pwqkvT, g_wqkvT);
    cudaGetSymbolAddress((void**)&pwoT,   g_woT);
    cudaGetSymbolAddress((void**)&pw1T,   g_w1T);
    cudaGetSymbolAddress((void**)&pw2T,   g_w2T);
    cudaGetSymbolAddress((void**)&pbqkv,  g_bqkv);

    cudaFuncSetAttribute(attn_tc,
        cudaFuncAttributeMaxDynamicSharedMemorySize, ATT_SMEM);
    cudaFuncSetAttribute(gemm_tc<0,0>,
        cudaFuncAttributeMaxDynamicSharedMemorySize, G_SMEM);
    cudaFuncSetAttribute(gemm_tc<0,1>,
        cudaFuncAttributeMaxDynamicSharedMemorySize, G_SMEM);
    cudaFuncSetAttribute(gemm_tc<1,1>,
        cudaFuncAttributeMaxDynamicSharedMemorySize, G_SMEM);

    // 0) transpose + round weights; concat qkv weights/biases
    dim3 tb(32, 8);
    transpose_round<<<dim3(H/32,  H/32),  tb>>>(wq, pwqkvT,             H, H);
    transpose_round<<<dim3(H/32,  H/32),  tb>>>(wk, pwqkvT + H*H,       H, H);
    transpose_round<<<dim3(H/32,  H/32),  tb>>>(wv, pwqkvT + 2*H*H,     H, H);
    transpose_round<<<dim3(H/32,  H/32),  tb>>>(wo, pwoT,               H, H);
    transpose_round<<<dim3(FF/32, H/32),  tb>>>(w1, pw1T,               H, FF);
    transpose_round<<<dim3(H/32,  FF/32), tb>>>(w2, pw2T,               FF, H);
    cudaMemcpyAsync(pbqkv,         bq, H*sizeof(float), cudaMemcpyDeviceToDevice);
    cudaMemcpyAsync(pbqkv + H,     bk, H*sizeof(float), cudaMemcpyDeviceToDevice);
    cudaMemcpyAsync(pbqkv + 2*H,   bv, H*sizeof(float), cudaMemcpyDeviceToDevice);

    // 1) LN1 (rounded)
    ln_kernel<1><<<ROWS, 256>>>(x, g1, be1, px1);

    // 2) fused QKV projection (rounded out)
    gemm_tc<0,1><<<dim3(H3/128, ROWS/128), 256, G_SMEM>>>(
        px1, pwqkvT, pbqkv, nullptr, pqkv, ROWS, H3, H);

    // 3) attention
    attn_tc<<<dim3(SEQ/32, NH, BB), 256, ATT_SMEM>>>(pqkv, out_w, pctx);

    // 4) output projection + residual(x)
    gemm_tc<0,0><<<dim3(H/128, ROWS/128), 256, G_SMEM>>>(
        pctx, pwoT, bo, x, pxres, ROWS, H, H);

    // 5) LN2 (rounded)
    ln_kernel<1><<<ROWS, 256>>>(pxres, g2, be2, px2);

    // 6) MLP
    gemm_tc<1,1><<<dim3(FF/128, ROWS/128), 256, G_SMEM>>>(
        px2, pw1T, b1, nullptr, ph, ROWS, FF, H);
    gemm_tc<0,0><<<dim3(H/128, ROWS/128), 256, G_SMEM>>>(
        ph, pw2T, b2, pxres, out_x, ROWS, H, FF);
}

// round 7
// speedup vs baseline: 3.3893x; 1.0011x over previous
#include <cuda_runtime.h>
#include <math.h>

#define H   768
#define NH  12
#define DH  64
#define FF  3072
#define BB  8
#define SEQ 1024
#define ROWS (BB*SEQ)                 // 8192
#define X_ELEMS ((size_t)ROWS*H)      // 6291456
#define H3  (3*H)                     // 2304

// ---------------- scratch (static device allocations; no cudaMalloc) ------
__device__ float g_x1[ROWS*H];
__device__ float g_qkv[ROWS*H3];
__device__ float g_ctx[ROWS*H];
__device__ float g_xres[ROWS*H];
__device__ float g_x2[ROWS*H];
__device__ float g_h [ROWS*FF];
// pre-rounded + transposed weights (W^T: [N][K])
__device__ float g_wqkvT[H3*H];
__device__ float g_woT[H*H];
__device__ float g_w1T[FF*H];
__device__ float g_w2T[H*FF];
__device__ float g_bqkv[H3];

// ---------------- helpers ----------------------------------------------------
__device__ __forceinline__ float rtf32(float f) {
    unsigned u;
    asm("cvt.rna.tf32.f32 %0, %1;" : "=r"(u) : "f"(f));
    return __uint_as_float(u);
}

__device__ __forceinline__ void cp16(unsigned saddr, const void* g) {
    asm volatile("cp.async.cg.shared.global [%0], [%1], 16;\n"
                 :: "r"(saddr), "l"(g));
}

__device__ __forceinline__ void ldsm4(unsigned* r, unsigned saddr) {
    asm volatile("ldmatrix.sync.aligned.m8n8.x4.shared.b16 {%0,%1,%2,%3}, [%4];\n"
                 : "=r"(r[0]), "=r"(r[1]), "=r"(r[2]), "=r"(r[3])
                 : "r"(saddr));
}

__device__ __forceinline__ void mma8(float* d, const unsigned* a, const unsigned* b) {
    asm volatile(
        "mma.sync.aligned.m16n8k8.row.col.f32.tf32.tf32.f32 "
        "{%0,%1,%2,%3}, {%4,%5,%6,%7}, {%8,%9}, {%0,%1,%2,%3};\n"
        : "+f"(d[0]), "+f"(d[1]), "+f"(d[2]), "+f"(d[3])
        : "r"(a[0]), "r"(a[1]), "r"(a[2]), "r"(a[3]), "r"(b[0]), "r"(b[1]));
}

__device__ __forceinline__ void mma8b(float* d, const unsigned* a,
                                      unsigned b0, unsigned b1) {
    asm volatile(
        "mma.sync.aligned.m16n8k8.row.col.f32.tf32.tf32.f32 "
        "{%0,%1,%2,%3}, {%4,%5,%6,%7}, {%8,%9}, {%0,%1,%2,%3};\n"
        : "+f"(d[0]), "+f"(d[1]), "+f"(d[2]), "+f"(d[3])
        : "r"(a[0]), "r"(a[1]), "r"(a[2]), "r"(a[3]), "r"(b0), "r"(b1));
}

// ---------------- fast exp (FMA pipe) --------------------------------------
__device__ __forceinline__ float fexp(float x) {
    x = fmaxf(x, -87.0f);
    float t  = x * 1.4426950408889634f;
    float fi = rintf(t);
    float z  = t - fi;
    float p  =            1.535336188319500e-4f;
    p = fmaf(p, z, 1.339887440266574e-3f);
    p = fmaf(p, z, 9.618437357674640e-3f);
    p = fmaf(p, z, 5.550332471162809e-2f);
    p = fmaf(p, z, 2.402264791363012e-1f);
    p = fmaf(p, z, 6.931472028550421e-1f);
    p = fmaf(p, z, 1.0f);
    return __int_as_float(((int)fi + 127) << 23) * p;
}

// ---------------- transpose helpers ------------------------------------------
__device__ __forceinline__ void tr_tile(const float* __restrict__ s,
                                        float* __restrict__ d,
                                        int K, int N, int kb, int nb,
                                        float (*t)[33]) {
    #pragma unroll
    for (int i = threadIdx.y; i < 32; i += 8)
        t[i][threadIdx.x] = s[(size_t)(kb + i) * N + nb + threadIdx.x];
    __syncthreads();
    #pragma unroll
    for (int i = threadIdx.y; i < 32; i += 8)
        d[(size_t)(nb + i) * K + kb + threadIdx.x] = rtf32(t[threadIdx.x][i]);
}

// qkv: 3 H x H weights -> g_wqkvT (z selects), bias concat folded in
__global__ __launch_bounds__(256) void transpose_qkv(
    const float* __restrict__ wq, const float* __restrict__ wk,
    const float* __restrict__ wv,
    const float* __restrict__ bq, const float* __restrict__ bk,
    const float* __restrict__ bv,
    float* __restrict__ dT, float* __restrict__ bqkv)
{
    __shared__ float t[32][33];
    int z = blockIdx.z;
    const float* s = (z == 0) ? wq : (z == 1) ? wk : wv;
    tr_tile(s, dT + (size_t)z * H * H, H, H, blockIdx.y * 32, blockIdx.x * 32, t);
    if (blockIdx.x == 0 && blockIdx.y == 0) {
        const float* bs = (z == 0) ? bq : (z == 1) ? bk : bv;
        int tid = threadIdx.y * 32 + threadIdx.x;
        for (int i = tid; i < H; i += 256) bqkv[z * H + i] = bs[i];
    }
}

// single weight transpose (wo)
__global__ __launch_bounds__(256) void transpose_round(
    const float* __restrict__ s, float* __restrict__ d, int K, int N)
{
    __shared__ float t[32][33];
    tr_tile(s, d, K, N, blockIdx.y * 32, blockIdx.x * 32, t);
}

// w1 (H x FF) and w2 (FF x H) fused; grid (FF/32, H/32, 2)
__global__ __launch_bounds__(256) void transpose_w12(
    const float* __restrict__ w1, const float* __restrict__ w2,
    float* __restrict__ w1T, float* __restrict__ w2T)
{
    __shared__ float t[32][33];
    if (blockIdx.z == 0)
        tr_tile(w1, w1T, H, FF, blockIdx.y * 32, blockIdx.x * 32, t);
    else
        tr_tile(w2, w2T, FF, H, blockIdx.x * 32, blockIdx.y * 32, t);
}

// ---------------- block reduce helper --------------------------------------
__device__ __forceinline__ float block_sum(float v, float* red) {
    #pragma unroll
    for (int o = 16; o; o >>= 1) v += __shfl_xor_sync(0xffffffffu, v, o);
    int w = threadIdx.x >> 5;
    if ((threadIdx.x & 31) == 0) red[w] = v;
    __syncthreads();
    float t = 0.0f;
    if (threadIdx.x < 32) {
        t = (threadIdx.x < 8) ? red[threadIdx.x] : 0.0f;
        #pragma unroll
        for (int o = 4; o; o >>= 1) t += __shfl_xor_sync(0xffffffffu, t, o);
        if (threadIdx.x == 0) red[0] = t;
    }
    __syncthreads();
    t = red[0];
    __syncthreads();
    return t;
}

// ---------------- layernorm -------------------------------------------------
template<int ROUND>
__global__ __launch_bounds__(256) void ln_kernel(
    const float* __restrict__ x, const float* __restrict__ g,
    const float* __restrict__ b, float* __restrict__ y)
{
    __shared__ float red[8];
    int row = blockIdx.x;
    const float* xr = x + (size_t)row * H;
    int t = threadIdx.x;
    float v0 = xr[t], v1 = xr[t + 256], v2 = xr[t + 512];
    float mu = block_sum(v0 + v1 + v2, red) * (1.0f / H);
    float d0 = v0 - mu, d1 = v1 - mu, d2 = v2 - mu;
    float var = block_sum(d0*d0 + d1*d1 + d2*d2, red) * (1.0f / H);
    float rs = rsqrtf(var + 1e-6f);
    float* yr = y + (size_t)row * H;
    float o0 = d0 * rs * g[t]       + b[t];
    float o1 = d1 * rs * g[t + 256] + b[t + 256];
    float o2 = d2 * rs * g[t + 512] + b[t + 512];
    if (ROUND) { o0 = rtf32(o0); o1 = rtf32(o1); o2 = rtf32(o2); }
    yr[t] = o0; yr[t + 256] = o1; yr[t + 512] = o2;
}

// ================= TF32 tensor-core GEMM (W transposed [N][K]) =============
#define ALD 36
#define STAGE_F (128*ALD)
#define STAGE_B (STAGE_F*4)
#define G_SMEM  (6*STAGE_B)                  // 110592 B

template<int ACT, int ROUND>
__global__ __launch_bounds__(256, 2) void gemm_tc(
    const float* __restrict__ A, const float* __restrict__ Wt,
    const float* __restrict__ bias, const float* __restrict__ res,
    float* __restrict__ C, int M, int N, int K)
{
    extern __shared__ float sm[];

    const int tid  = threadIdx.x;
    const int wid  = tid >> 5;
    const int lane = tid & 31;
    const int g    = lane >> 2;
    const int tg   = lane & 3;

    const int m0 = blockIdx.y * 128;
    const int n0 = blockIdx.x * 128;
    const int wm = (wid & 3) * 32;
    const int wn = (wid >> 2) * 64;

    unsigned sbase = (unsigned)__cvta_generic_to_shared(sm);

    unsigned aS[4], bS[4];
    const float* aG[4];
    const float* bG[4];
    #pragma unroll
    for (int i = 0; i < 4; i++) {
        int c = tid + 256 * i;
        int r = c >> 3, cc = (c & 7) * 4;
        aS[i] = sbase + (unsigned)(r * ALD + cc) * 4;
        aG[i] = A  + (size_t)(m0 + r) * K + cc;
        bS[i] = sbase + 3 * STAGE_B + (unsigned)(r * ALD + cc) * 4;
        bG[i] = Wt + (size_t)(n0 + r) * K + cc;
    }

    const int rsel = (lane >> 3) & 1;
    const int csel = (lane >> 4) & 1;
    unsigned aOff[2], bOff[4];
    #pragma unroll
    for (int mt = 0; mt < 2; mt++) {
        int rowA = wm + mt * 16 + (lane & 7) + rsel * 8;
        aOff[mt] = (unsigned)(rowA * ALD + csel * 4) * 4;
    }
    #pragma unroll
    for (int p = 0; p < 4; p++) {
        int rowB = wn + p * 16 + (lane & 7) + rsel * 8;
        bOff[p] = (unsigned)(rowB * ALD + csel * 4) * 4;
    }

    float d[2][8][4];
    #pragma unroll
    for (int mt = 0; mt < 2; mt++)
        #pragma unroll
        for (int nt = 0; nt < 8; nt++)
            #pragma unroll
            for (int r = 0; r < 4; r++) d[mt][nt][r] = 0.0f;

    const int KIT = K >> 5;

    auto fill = [&](int it, int s) {
        unsigned so = (unsigned)s * STAGE_B;
        int k0 = it * 32;
        #pragma unroll
        for (int i = 0; i < 4; i++) cp16(aS[i] + so, aG[i] + k0);
        #pragma unroll
        for (int i = 0; i < 4; i++) cp16(bS[i] + so, bG[i] + k0);
    };

    fill(0, 0); asm volatile("cp.async.commit_group;\n");
    fill(1, 1); asm volatile("cp.async.commit_group;\n");

    int s = 0;
    for (int it = 0; it < KIT; it++) {
        asm volatile("cp.async.wait_group 1;\n");
        __syncthreads();
        if (it + 2 < KIT) {
            int s2 = s + 2; if (s2 >= 3) s2 -= 3;
            fill(it + 2, s2);
        }
        asm volatile("cp.async.commit_group;\n");

        const unsigned aStage = sbase + (unsigned)s * STAGE_B;
        const unsigned bStage = sbase + 3 * STAGE_B + (unsigned)s * STAGE_B;
        #pragma unroll
        for (int kk = 0; kk < 4; kk++) {
            unsigned a[2][4], bb[4][4];
            ldsm4(a[0], aStage + aOff[0] + kk * 32);
            ldsm4(a[1], aStage + aOff[1] + kk * 32);
            #pragma unroll
            for (int p = 0; p < 4; p++)
                ldsm4(bb[p], bStage + bOff[p] + kk * 32);
            #pragma unroll
            for (int mt = 0; mt < 2; mt++)
                #pragma unroll
                for (int nt = 0; nt < 8; nt++) {
                    int p = nt >> 1, od = nt & 1;
                    mma8b(d[mt][nt], a[mt], bb[p][od], bb[p][od + 2]);
                }
        }
        if (++s >= 3) s = 0;
    }

    #pragma unroll
    for (int mt = 0; mt < 2; mt++) {
        int r0 = m0 + wm + mt * 16 + g;
        #pragma unroll
        for (int nt = 0; nt < 8; nt++) {
            int c = n0 + wn + nt * 8 + 2 * tg;
            float b0 = bias[c], b1 = bias[c + 1];
            #pragma unroll
            for (int half = 0; half < 2; half++) {
                int row = r0 + half * 8;
                size_t base = (size_t)row * N + c;
                float v0 = d[mt][nt][2 * half]     + b0;
                float v1 = d[mt][nt][2 * half + 1] + b1;
                if (ACT == 1) {
                    v0 = 0.5f * v0 * (1.0f + erff(v0 * 0.70710678118654752f));
                    v1 = 0.5f * v1 * (1.0f + erff(v1 * 0.70710678118654752f));
                }
                if (res) { v0 += res[base]; v1 += res[base + 1]; }
                if (ROUND) { v0 = rtf32(v0); v1 = rtf32(v1); }
                float2 o; o.x = v0; o.y = v1;
                *(float2*)(C + base) = o;
            }
        }
    }
}

// ================= tensor-core fused attention (ldmatrix fragments) =========
#define KV_LD 68
#define SS_LD 1028
#define ATT_SMEM ((32*KV_LD + 2*128*KV_LD + 32*SS_LD) * 4)   // 210048 B

__device__ __forceinline__ void load_kv(unsigned skv, const float* gp,
                                        int chunk, int buf, int tid) {
    #pragma unroll
    for (int i = 0; i < 8; i++) {
        int idx = tid + 256 * i;
        int r = idx >> 4, c = (idx & 15) * 4;
        cp16(skv + (unsigned)(buf * 128 * KV_LD + r * KV_LD + c) * 4,
             gp + (size_t)(chunk * 128 + r) * H3 + c);
    }
}

__global__ __launch_bounds__(256) void attn_tc(
    const float* __restrict__ QKV, float* __restrict__ Wout,
    float* __restrict__ Ctx)
{
    extern __shared__ float sm[];
    float* sQ  = sm;
    float* sKV = sQ + 32 * KV_LD;
    float* sS  = sKV + 2 * 128 * KV_LD;

    const int tid  = threadIdx.x;
    const int wid  = tid >> 5;
    const int lane = tid & 31;
    const int g    = lane >> 2;
    const int tg   = lane & 3;
    const int q0   = blockIdx.x * 32;
    const int h    = blockIdx.y;
    const int b    = blockIdx.z;
    const float scale = 0.03608439182435161f;   // 1/sqrt(768)

    const size_t rowb = (size_t)b * SEQ * H3;
    const float* Qp = QKV + rowb + (size_t)q0 * H3 + h * DH;
    const float* Kp = QKV + rowb + H  + h * DH;
    const float* Vp = QKV + rowb + 2 * H + h * DH;

    unsigned sQb  = (unsigned)__cvta_generic_to_shared(sQ);
    unsigned sKVb = (unsigned)__cvta_generic_to_shared(sKV);
    unsigned sSb  = (unsigned)__cvta_generic_to_shared(sS);

    // ldmatrix lane-pattern selectors
    const int rsel = (lane >> 3) & 1;
    const int csel = (lane >> 4) & 1;
    // K-fragment offset (rows wid*16..+15 of KV buffer), +ks*32B per 8-k step
    const unsigned kOff =
        (unsigned)(((wid * 16 + (lane & 7) + rsel * 8) * KV_LD + csel * 4) * 4);
    // P-fragment offsets (rows mt*16..+15 of sS), +kcol*4B per k position
    unsigned pOff[2];
    pOff[0] = (unsigned)((((lane & 7) + rsel * 8) * SS_LD + csel * 4) * 4);
    pOff[1] = pOff[0] + (unsigned)(16 * SS_LD * 4);

    #pragma unroll
    for (int i = 0; i < 2; i++) {
        int idx = tid + 256 * i;
        int r = idx >> 4, c = (idx & 15) * 4;
        cp16(sQb + (unsigned)(r * KV_LD + c) * 4, Qp + (size_t)r * H3 + c);
    }
    load_kv(sKVb, Kp, 0, 0, tid);
    asm volatile("cp.async.commit_group;\n");
    load_kv(sKVb, Kp, 1, 1, tid);
    asm volatile("cp.async.commit_group;\n");
    asm volatile("cp.async.wait_group 1;\n");
    __syncthreads();

    // Q fragments in registers (already tf32-rounded bits)
    unsigned qf[2][8][4];
    #pragma unroll
    for (int ks = 0; ks < 8; ks++)
        #pragma unroll
        for (int mt = 0; mt < 2; mt++) {
            const float* Qr = sQ + (g + mt * 16) * KV_LD + ks * 8 + tg;
            qf[mt][ks][0] = __float_as_uint(Qr[0]);
            qf[mt][ks][1] = __float_as_uint(Qr[8 * KV_LD]);
            qf[mt][ks][2] = __float_as_uint(Qr[4]);
            qf[mt][ks][3] = __float_as_uint(Qr[8 * KV_LD + 4]);
        }

    // ---- phase 1: scores (K fragments via ldmatrix) ----
    for (int jt = 0; jt < 8; jt++) {
        const unsigned Kbuf = sKVb + (unsigned)((jt & 1) * 128 * KV_LD * 4);
        float acc[2][2][4];
        #pragma unroll
        for (int mt = 0; mt < 2; mt++)
            #pragma unroll
            for (int nt = 0; nt < 2; nt++)
                #pragma unroll
                for (int r = 0; r < 4; r++) acc[mt][nt][r] = 0.0f;
        #pragma unroll
        for (int ks = 0; ks < 8; ks++) {
            unsigned bb[4];
            ldsm4(bb, Kbuf + kOff + ks * 32);
            #pragma unroll
            for (int mt = 0; mt < 2; mt++) {
                mma8b(acc[mt][0], qf[mt][ks], bb[0], bb[2]);
                mma8b(acc[mt][1], qf[mt][ks], bb[1], bb[3]);
            }
        }
        #pragma unroll
        for (int mt = 0; mt < 2; mt++)
            #pragma unroll
            for (int nt = 0; nt < 2; nt++) {
                int col = jt * 128 + wid * 16 + nt * 8 + 2 * tg;
                int r1 = g + mt * 16;
                float2 o0; o0.x = acc[mt][nt][0] * scale; o0.y = acc[mt][nt][1] * scale;
                float2 o1; o1.x = acc[mt][nt][2] * scale; o1.y = acc[mt][nt][3] * scale;
                *(float2*)&sS[r1 * SS_LD + col]       = o0;
                *(float2*)&sS[(r1 + 8) * SS_LD + col] = o1;
            }
        __syncthreads();
        if (jt < 6) {
            load_kv(sKVb, Kp, jt + 2, jt & 1, tid);
            asm volatile("cp.async.commit_group;\n");
        }
        if (jt < 7) {
            if (jt < 6) asm volatile("cp.async.wait_group 1;\n");
            else        asm volatile("cp.async.wait_group 0;\n");
            __syncthreads();
        }
    }

    load_kv(sKVb, Vp, 0, 0, tid);
    asm volatile("cp.async.commit_group;\n");

    // ---- phase 2: softmax ----
    {
        for (int rr = 0; rr < 4; rr++) {
            float* srow = &sS[(wid + rr * 8) * SS_LD];
            float m = -1e30f;
            for (int t = lane; t < SEQ; t += 32) m = fmaxf(m, srow[t]);
            #pragma unroll
            for (int o = 16; o; o >>= 1) m = fmaxf(m, __shfl_xor_sync(0xffffffffu, m, o));
            float ssum = 0.0f;
            for (int t = lane; t < SEQ; t += 32) {
                float e = fexp(srow[t] - m);
                srow[t] = e;
                ssum += e;
            }
            #pragma unroll
            for (int o = 16; o; o >>= 1) ssum += __shfl_xor_sync(0xffffffffu, ssum, o);
            float inv = 1.0f / ssum;
            for (int t = lane; t < SEQ; t += 32) srow[t] *= inv;
        }
    }
    __syncthreads();

    // ---- phase 3: write weights (f32) + round P in smem to tf32 ----
    {
        float* Wrow = Wout + ((size_t)(b * NH + h) * SEQ + q0) * SEQ;
        for (int s = tid; s < 32 * 256; s += 256) {
            int r = s >> 8, c4 = (s & 255) * 4;
            float4 v = *(const float4*)&sS[r * SS_LD + c4];
            *(float4*)(Wrow + (size_t)r * SEQ + c4) = v;
            v.x = rtf32(v.x); v.y = rtf32(v.y); v.z = rtf32(v.z); v.w = rtf32(v.w);
            *(float4*)&sS[r * SS_LD + c4] = v;
        }
    }
    __syncthreads();

    load_kv(sKVb, Vp, 1, 1, tid);
    asm volatile("cp.async.commit_group;\n");
    asm volatile("cp.async.wait_group 1;\n");
    __syncthreads();

    // ---- phase 4: ctx = P @ V (P fragments via ldmatrix) ----
    float acc2[2][4];
    #pragma unroll
    for (int mt = 0; mt < 2; mt++)
        #pragma unroll
        for (int r = 0; r < 4; r++) acc2[mt][r] = 0.0f;

    for (int kt = 0; kt < 8; kt++) {
        const float* Vb = sKV + (kt & 1) * 128 * KV_LD;
        #pragma unroll 4
        for (int ks = 0; ks < 16; ks++) {
            int kcol = kt * 128 + ks * 8;
            unsigned bf[2];
            bf[0] = __float_as_uint(Vb[(ks * 8 + tg)     * KV_LD + wid * 8 + g]);
            bf[1] = __float_as_uint(Vb[(ks * 8 + tg + 4) * KV_LD + wid * 8 + g]);
            #pragma unroll
            for (int mt = 0; mt < 2; mt++) {
                unsigned af[4];
                ldsm4(af, sSb + pOff[mt] + (unsigned)(kcol * 4));
                mma8(acc2[mt], af, bf);
            }
        }
        __syncthreads();
        if (kt < 6) {
            load_kv(sKVb, Vp, kt + 2, kt & 1, tid);
            asm volatile("cp.async.commit_group;\n");
        }
        if (kt < 7) {
            if (kt < 6) asm volatile("cp.async.wait_group 1;\n");
            else        asm volatile("cp.async.wait_group 0;\n");
            __syncthreads();
        }
    }

    #pragma unroll
    for (int mt = 0; mt < 2; mt++)
        #pragma unroll
        for (int half = 0; half < 2; half++) {
            int row = q0 + g + mt * 16 + half * 8;
            int col = h * DH + wid * 8 + 2 * tg;
            float2 o;
            o.x = rtf32(acc2[mt][2 * half]);
            o.y = rtf32(acc2[mt][2 * half + 1]);
            *(float2*)(Ctx + ((size_t)b * SEQ + row) * H + col) = o;
        }
}

// ---------------- launch ---------------------------------------------------
extern "C" void kernel_launch(void* const* d_in, const int* in_sizes, int n_in,
                              void* d_out, int out_size)
{
    const float* x   = (const float*)d_in[0];
    const float* wq  = (const float*)d_in[1];
    const float* bq  = (const float*)d_in[2];
    const float* wk  = (const float*)d_in[3];
    const float* bk  = (const float*)d_in[4];
    const float* wv  = (const float*)d_in[5];
    const float* bv  = (const float*)d_in[6];
    const float* wo  = (const float*)d_in[7];
    const float* bo  = (const float*)d_in[8];
    const float* w1  = (const float*)d_in[9];
    const float* b1  = (const float*)d_in[10];
    const float* w2  = (const float*)d_in[11];
    const float* b2  = (const float*)d_in[12];
    const float* g1  = (const float*)d_in[13];
    const float* be1 = (const float*)d_in[14];
    const float* g2  = (const float*)d_in[15];
    const float* be2 = (const float*)d_in[16];

    float* out_x = (float*)d_out;
    float* out_w = (float*)d_out + X_ELEMS;

    float *px1, *pqkv, *pctx, *pxres, *px2, *ph;
    float *pwqkvT, *pwoT, *pw1T, *pw2T, *pbqkv;
    cudaGetSymbolAddress((void**)&px1,    g_x1);
    cudaGetSymbolAddress((void**)&pqkv,   g_qkv);
    cudaGetSymbolAddress((void**)&pctx,   g_ctx);
    cudaGetSymbolAddress((void**)&pxres,  g_xres);
    cudaGetSymbolAddress((void**)&px2,    g_x2);
    cudaGetSymbolAddress((void**)&ph,     g_h);
    cudaGetSymbolAddress((void**)&pwqkvT, g_wqkvT);
    cudaGetSymbolAddress((void**)&pwoT,   g_woT);
    cudaGetSymbolAddress((void**)&pw1T,   g_w1T);
    cudaGetSymbolAddress((void**)&pw2T,   g_w2T);
    cudaGetSymbolAddress((void**)&pbqkv,  g_bqkv);

    cudaFuncSetAttribute(attn_tc,
        cudaFuncAttributeMaxDynamicSharedMemorySize, ATT_SMEM);
    cudaFuncSetAttribute(gemm_tc<0,0>,
        cudaFuncAttributeMaxDynamicSharedMemorySize, G_SMEM);
    cudaFuncSetAttribute(gemm_tc<0,1>,
        cudaFuncAttributeMaxDynamicSharedMemorySize, G_SMEM);
    cudaFuncSetAttribute(gemm_tc<1,1>,
        cudaFuncAttributeMaxDynamicSharedMemorySize, G_SMEM);

    dim3 tb(32, 8);

    // launch #0: qkv weight transpose + bias concat
    transpose_qkv<<<dim3(H/32, H/32, 3), tb>>>(wq, wk, wv, bq, bk, bv,
                                               pwqkvT, pbqkv);
    // launch #1: LN1 (rounded)
    ln_kernel<1><<<ROWS, 256>>>(x, g1, be1, px1);
    // launch #2: fused QKV projection (rounded out)
    gemm_tc<0,1><<<dim3(H3/128, ROWS/128), 256, G_SMEM>>>(
        px1, pwqkvT, pbqkv, nullptr, pqkv, ROWS, H3, H);
    // launch #3: wo transpose
    transpose_round<<<dim3(H/32, H/32), tb>>>(wo, pwoT, H, H);
    // launch #4: w1+w2 transpose
    transpose_w12<<<dim3(FF/32, H/32, 2), tb>>>(w1, w2, pw1T, pw2T);
    // launch #5 (ncu capture target): attention
    attn_tc<<<dim3(SEQ/32, NH, BB), 256, ATT_SMEM>>>(pqkv, out_w, pctx);
    // launch #6: output projection + residual(x)
    gemm_tc<0,0><<<dim3(H/128, ROWS/128), 256, G_SMEM>>>(
        pctx, pwoT, bo, x, pxres, ROWS, H, H);
    // launch #7: LN2 (rounded)
    ln_kernel<1><<<ROWS, 256>>>(pxres, g2, be2, px2);
    // launch #8: MLP up + gelu
    gemm_tc<1,1><<<dim3(FF/128, ROWS/128), 256, G_SMEM>>>(
        px2, pw1T, b1, nullptr, ph, ROWS, FF, H);
    // launch #9: MLP down + residual
    gemm_tc<0,0><<<dim3(H/128, ROWS/128), 256, G_SMEM>>>(
        ph, pw2T, b2, pxres, out_x, ROWS, H, FF);
}

// round 8
// speedup vs baseline: 5.2688x; 1.5546x over previous
#include <cuda_runtime.h>
#include <cuda_fp16.h>
#include <math.h>

#define H   768
#define NH  12
#define DH  64
#define FF  3072
#define BB  8
#define SEQ 1024
#define ROWS (BB*SEQ)                 // 8192
#define X_ELEMS ((size_t)ROWS*H)      // 6291456
#define H3  (3*H)                     // 2304

// ---------------- scratch (static device allocations) -----------------------
__device__ __half g_x1h [ROWS*H];
__device__ __half g_qkvh[ROWS*H3];
__device__ __half g_ctxh[ROWS*H];
__device__ float  g_xres[ROWS*H];
__device__ __half g_x2h [ROWS*H];
__device__ __half g_hh  [ROWS*FF];
// transposed fp16 weights (W^T: [N][K])
__device__ __half g_wqkvT[H3*H];
__device__ __half g_woT [H*H];
__device__ __half g_w1T [FF*H];
__device__ __half g_w2T [H*FF];
__device__ float  g_bqkv[H3];

// ---------------- helpers ----------------------------------------------------
__device__ __forceinline__ void cp16(unsigned saddr, const void* g) {
    asm volatile("cp.async.cg.shared.global [%0], [%1], 16;\n"
                 :: "r"(saddr), "l"(g));
}

__device__ __forceinline__ void ldsm4(unsigned* r, unsigned saddr) {
    asm volatile("ldmatrix.sync.aligned.m8n8.x4.shared.b16 {%0,%1,%2,%3}, [%4];\n"
                 : "=r"(r[0]), "=r"(r[1]), "=r"(r[2]), "=r"(r[3])
                 : "r"(saddr));
}

__device__ __forceinline__ void ldsm2t(unsigned* r, unsigned saddr) {
    asm volatile("ldmatrix.sync.aligned.m8n8.x2.trans.shared.b16 {%0,%1}, [%2];\n"
                 : "=r"(r[0]), "=r"(r[1])
                 : "r"(saddr));
}

// fp16 mma: D(16x8,f32) += A(16x16,f16) * B(16x8,f16)
__device__ __forceinline__ void mma16(float* d, const unsigned* a,
                                      unsigned b0, unsigned b1) {
    asm volatile(
        "mma.sync.aligned.m16n8k16.row.col.f32.f16.f16.f32 "
        "{%0,%1,%2,%3}, {%4,%5,%6,%7}, {%8,%9}, {%0,%1,%2,%3};\n"
        : "+f"(d[0]), "+f"(d[1]), "+f"(d[2]), "+f"(d[3])
        : "r"(a[0]), "r"(a[1]), "r"(a[2]), "r"(a[3]), "r"(b0), "r"(b1));
}

// ---------------- fast exp (FMA pipe) --------------------------------------
__device__ __forceinline__ float fexp(float x) {
    x = fmaxf(x, -87.0f);
    float t  = x * 1.4426950408889634f;
    float fi = rintf(t);
    float z  = t - fi;
    float p  =            1.535336188319500e-4f;
    p = fmaf(p, z, 1.339887440266574e-3f);
    p = fmaf(p, z, 9.618437357674640e-3f);
    p = fmaf(p, z, 5.550332471162809e-2f);
    p = fmaf(p, z, 2.402264791363012e-1f);
    p = fmaf(p, z, 6.931472028550421e-1f);
    p = fmaf(p, z, 1.0f);
    return __int_as_float(((int)fi + 127) << 23) * p;
}

// ---------------- transpose helpers (f32 [K][N] -> f16 [N][K]) ---------------
__device__ __forceinline__ void tr_tile(const float* __restrict__ s,
                                        __half* __restrict__ d,
                                        int K, int N, int kb, int nb,
                                        float (*t)[33]) {
    #pragma unroll
    for (int i = threadIdx.y; i < 32; i += 8)
        t[i][threadIdx.x] = s[(size_t)(kb + i) * N + nb + threadIdx.x];
    __syncthreads();
    #pragma unroll
    for (int i = threadIdx.y; i < 32; i += 8)
        d[(size_t)(nb + i) * K + kb + threadIdx.x] = __float2half(t[threadIdx.x][i]);
}

__global__ __launch_bounds__(256) void transpose_qkv(
    const float* __restrict__ wq, const float* __restrict__ wk,
    const float* __restrict__ wv,
    const float* __restrict__ bq, const float* __restrict__ bk,
    const float* __restrict__ bv,
    __half* __restrict__ dT, float* __restrict__ bqkv)
{
    __shared__ float t[32][33];
    int z = blockIdx.z;
    const float* s = (z == 0) ? wq : (z == 1) ? wk : wv;
    tr_tile(s, dT + (size_t)z * H * H, H, H, blockIdx.y * 32, blockIdx.x * 32, t);
    if (blockIdx.x == 0 && blockIdx.y == 0) {
        const float* bs = (z == 0) ? bq : (z == 1) ? bk : bv;
        int tid = threadIdx.y * 32 + threadIdx.x;
        for (int i = tid; i < H; i += 256) bqkv[z * H + i] = bs[i];
    }
}

__global__ __launch_bounds__(256) void transpose_one(
    const float* __restrict__ s, __half* __restrict__ d, int K, int N)
{
    __shared__ float t[32][33];
    tr_tile(s, d, K, N, blockIdx.y * 32, blockIdx.x * 32, t);
}

__global__ __launch_bounds__(256) void transpose_w12(
    const float* __restrict__ w1, const float* __restrict__ w2,
    __half* __restrict__ w1T, __half* __restrict__ w2T)
{
    __shared__ float t[32][33];
    if (blockIdx.z == 0)
        tr_tile(w1, w1T, H, FF, blockIdx.y * 32, blockIdx.x * 32, t);
    else
        tr_tile(w2, w2T, FF, H, blockIdx.x * 32, blockIdx.y * 32, t);
}

// ---------------- block reduce -----------------------------------------------
__device__ __forceinline__ float block_sum(float v, float* red) {
    #pragma unroll
    for (int o = 16; o; o >>= 1) v += __shfl_xor_sync(0xffffffffu, v, o);
    int w = threadIdx.x >> 5;
    if ((threadIdx.x & 31) == 0) red[w] = v;
    __syncthreads();
    float t = 0.0f;
    if (threadIdx.x < 32) {
        t = (threadIdx.x < 8) ? red[threadIdx.x] : 0.0f;
        #pragma unroll
        for (int o = 4; o; o >>= 1) t += __shfl_xor_sync(0xffffffffu, t, o);
        if (threadIdx.x == 0) red[0] = t;
    }
    __syncthreads();
    t = red[0];
    __syncthreads();
    return t;
}

// ---------------- layernorm: f32 in -> f16 out -------------------------------
__global__ __launch_bounds__(256) void ln_kernel(
    const float* __restrict__ x, const float* __restrict__ g,
    const float* __restrict__ b, __half* __restrict__ y)
{
    __shared__ float red[8];
    int row = blockIdx.x;
    const float* xr = x + (size_t)row * H;
    int t = threadIdx.x;
    float v0 = xr[t], v1 = xr[t + 256], v2 = xr[t + 512];
    float mu = block_sum(v0 + v1 + v2, red) * (1.0f / H);
    float d0 = v0 - mu, d1 = v1 - mu, d2 = v2 - mu;
    float var = block_sum(d0*d0 + d1*d1 + d2*d2, red) * (1.0f / H);
    float rs = rsqrtf(var + 1e-6f);
    __half* yr = y + (size_t)row * H;
    yr[t]       = __float2half(d0 * rs * g[t]       + b[t]);
    yr[t + 256] = __float2half(d1 * rs * g[t + 256] + b[t + 256]);
    yr[t + 512] = __float2half(d2 * rs * g[t + 512] + b[t + 512]);
}

// ================= FP16 tensor-core GEMM (W transposed [N][K]) ==============
// BM=128 BN=128 BK=64(half), 8 warps (4m x 2n), warp tile 32x64.
// 3-stage cp.async ring. OUT: 0=f32+bias+res, 1=f16(bias), 2=gelu->f16.
#define ALD 72                                  // halves per row (64 + 8 pad)
#define STAGE_B (128*ALD*2)                     // 18432 bytes per operand stage
#define G_SMEM  (6*STAGE_B)                     // 110592 B

template<int OUT>
__global__ __launch_bounds__(256, 2) void gemm_tc(
    const __half* __restrict__ A, const __half* __restrict__ Wt,
    const float* __restrict__ bias, const float* __restrict__ res,
    void* __restrict__ Cout, int M, int N, int K)
{
    extern __shared__ char smc[];

    const int tid  = threadIdx.x;
    const int wid  = tid >> 5;
    const int lane = tid & 31;
    const int g    = lane >> 2;
    const int tg   = lane & 3;

    const int m0 = blockIdx.y * 128;
    const int n0 = blockIdx.x * 128;
    const int wm = (wid & 3) * 32;
    const int wn = (wid >> 2) * 64;

    unsigned sbase = (unsigned)__cvta_generic_to_shared(smc);

    // cp.async maps: 128 rows x 64 halves = 1024 16B-chunks per operand
    unsigned aS[4], bS[4];
    const __half* aG[4];
    const __half* bG[4];
    #pragma unroll
    for (int i = 0; i < 4; i++) {
        int c = tid + 256 * i;
        int r = c >> 3, cc = (c & 7) * 8;
        aS[i] = sbase + (unsigned)(r * ALD + cc) * 2;
        aG[i] = A  + (size_t)(m0 + r) * K + cc;
        bS[i] = sbase + 3 * STAGE_B + (unsigned)(r * ALD + cc) * 2;
        bG[i] = Wt + (size_t)(n0 + r) * K + cc;
    }

    const int rsel = (lane >> 3) & 1;
    const int csel = (lane >> 4) & 1;
    unsigned aOff[2], bOff[4];
    #pragma unroll
    for (int mt = 0; mt < 2; mt++)
        aOff[mt] = (unsigned)(((wm + mt * 16 + (lane & 7) + rsel * 8) * ALD
                               + csel * 8) * 2);
    #pragma unroll
    for (int p = 0; p < 4; p++)
        bOff[p] = (unsigned)(((wn + p * 16 + (lane & 7) + rsel * 8) * ALD
                              + csel * 8) * 2);

    float d[2][8][4];
    #pragma unroll
    for (int mt = 0; mt < 2; mt++)
        #pragma unroll
        for (int nt = 0; nt < 8; nt++)
            #pragma unroll
            for (int r = 0; r < 4; r++) d[mt][nt][r] = 0.0f;

    const int KIT = K >> 6;

    auto fill = [&](int it, int st) {
        unsigned so = (unsigned)st * STAGE_B;
        int k0 = it * 64;
        #pragma unroll
        for (int i = 0; i < 4; i++) cp16(aS[i] + so, aG[i] + k0);
        #pragma unroll
        for (int i = 0; i < 4; i++) cp16(bS[i] + so, bG[i] + k0);
    };

    fill(0, 0); asm volatile("cp.async.commit_group;\n");
    fill(1, 1); asm volatile("cp.async.commit_group;\n");

    int st = 0;
    for (int it = 0; it < KIT; it++) {
        asm volatile("cp.async.wait_group 1;\n");
        __syncthreads();
        if (it + 2 < KIT) {
            int s2 = st + 2; if (s2 >= 3) s2 -= 3;
            fill(it + 2, s2);
        }
        asm volatile("cp.async.commit_group;\n");

        const unsigned aStage = sbase + (unsigned)st * STAGE_B;
        const unsigned bStage = sbase + 3 * STAGE_B + (unsigned)st * STAGE_B;
        #pragma unroll
        for (int kk = 0; kk < 4; kk++) {     // 4 x k16 per 64-half chunk
            unsigned a[2][4], bb[4][4];
            ldsm4(a[0], aStage + aOff[0] + kk * 32);
            ldsm4(a[1], aStage + aOff[1] + kk * 32);
            #pragma unroll
            for (int p = 0; p < 4; p++)
                ldsm4(bb[p], bStage + bOff[p] + kk * 32);
            #pragma unroll
            for (int mt = 0; mt < 2; mt++)
                #pragma unroll
                for (int nt = 0; nt < 8; nt++) {
                    int p = nt >> 1, od = nt & 1;
                    mma16(d[mt][nt], a[mt], bb[p][od], bb[p][od + 2]);
                }
        }
        if (++st >= 3) st = 0;
    }

    #pragma unroll
    for (int mt = 0; mt < 2; mt++) {
        int r0 = m0 + wm + mt * 16 + g;
        #pragma unroll
        for (int nt = 0; nt < 8; nt++) {
            int c = n0 + wn + nt * 8 + 2 * tg;
            float b0 = bias[c], b1 = bias[c + 1];
            #pragma unroll
            for (int half = 0; half < 2; half++) {
                int row = r0 + half * 8;
                size_t base = (size_t)row * N + c;
                float v0 = d[mt][nt][2 * half]     + b0;
                float v1 = d[mt][nt][2 * half + 1] + b1;
                if (OUT == 2) {
                    v0 = 0.5f * v0 * (1.0f + erff(v0 * 0.70710678118654752f));
                    v1 = 0.5f * v1 * (1.0f + erff(v1 * 0.70710678118654752f));
                }
                if (OUT == 0) {
                    v0 += res[base]; v1 += res[base + 1];
                    float2 o; o.x = v0; o.y = v1;
                    *(float2*)((float*)Cout + base) = o;
                } else {
                    *(__half2*)((__half*)Cout + base) = __floats2half2_rn(v0, v1);
                }
            }
        }
    }
}

// ================= fp16 tensor-core fused attention ==========================
// QKV fp16 packed rows (stride H3). sS fp32 scores; P overlaid as fp16.
#define KV_LD 72
#define KVBUF_B (128*KV_LD*2)                    // 18432 B
#define SS_LD 1028
#define SP_LD 1032
#define SM_Q   0
#define SM_KV  4608
#define SM_S   (SM_KV + 2*KVBUF_B)               // 41472
#define ATT_SMEM (SM_S + 32*SS_LD*4)             // 173056 B

__device__ __forceinline__ void load_kv(unsigned skv, const __half* gp,
                                        int chunk, int buf, int tid) {
    #pragma unroll
    for (int i = 0; i < 4; i++) {
        int idx = tid + 256 * i;
        int r = idx >> 3, cc = (idx & 7) * 8;
        cp16(skv + (unsigned)(buf * KVBUF_B) + (unsigned)(r * KV_LD + cc) * 2,
             gp + (size_t)(chunk * 128 + r) * H3 + cc);
    }
}

__global__ __launch_bounds__(256) void attn_tc(
    const __half* __restrict__ QKV, float* __restrict__ Wout,
    __half* __restrict__ Ctx)
{
    extern __shared__ char smc[];
    float* sS  = (float*)(smc + SM_S);
    __half* sP = (__half*)(smc + SM_S);    // fp16 overlay after conversion

    const int tid  = threadIdx.x;
    const int wid  = tid >> 5;
    const int lane = tid & 31;
    const int g    = lane >> 2;
    const int tg   = lane & 3;
    const int q0   = blockIdx.x * 32;
    const int h    = blockIdx.y;
    const int b    = blockIdx.z;
    const float scale = 0.03608439182435161f;   // 1/sqrt(768)

    const size_t rowb = (size_t)b * SEQ * H3;
    const __half* Qp = QKV + rowb + (size_t)q0 * H3 + h * DH;
    const __half* Kp = QKV + rowb + H  + h * DH;
    const __half* Vp = QKV + rowb + 2 * H + h * DH;

    unsigned sbase = (unsigned)__cvta_generic_to_shared(smc);
    unsigned sQb  = sbase + SM_Q;
    unsigned sKVb = sbase + SM_KV;
    unsigned sPb  = sbase + SM_S;

    const int rsel = (lane >> 3) & 1;
    const int csel = (lane >> 4) & 1;
    // K-fragment base (rows wid*16..+15 of KV buffer)
    const unsigned kOff =
        (unsigned)(((wid * 16 + (lane & 7) + rsel * 8) * KV_LD + csel * 8) * 2);
    // Q/P-fragment bases per m-tile
    unsigned qOff[2], pOff[2];
    #pragma unroll
    for (int mt = 0; mt < 2; mt++) {
        int ra = mt * 16 + (lane & 7) + rsel * 8;
        qOff[mt] = (unsigned)((ra * KV_LD + csel * 8) * 2);
        pOff[mt] = (unsigned)((ra * SP_LD + csel * 8) * 2);
    }
    // V-fragment (trans) base: rows = k, cols = wid*8..+7
    const unsigned vOff = (unsigned)(((lane & 15) * KV_LD + wid * 8) * 2);

    // load Q tile (32 rows x 64 halves = 256 chunks)
    {
        int r = tid >> 3, cc = (tid & 7) * 8;
        cp16(sQb + (unsigned)(r * KV_LD + cc) * 2, Qp + (size_t)r * H3 + cc);
    }
    load_kv(sKVb, Kp, 0, 0, tid);
    asm volatile("cp.async.commit_group;\n");
    load_kv(sKVb, Kp, 1, 1, tid);
    asm volatile("cp.async.commit_group;\n");
    asm volatile("cp.async.wait_group 1;\n");
    __syncthreads();

    // Q fragments (4 k16-steps over DH=64)
    unsigned qf[2][4][4];
    #pragma unroll
    for (int ks = 0; ks < 4; ks++)
        #pragma unroll
        for (int mt = 0; mt < 2; mt++)
            ldsm4(qf[mt][ks], sQb + qOff[mt] + ks * 32);

    // ---- phase 1: scores ----
    for (int jt = 0; jt < 8; jt++) {
        const unsigned Kbuf = sKVb + (unsigned)((jt & 1) * KVBUF_B);
        float acc[2][2][4];
        #pragma unroll
        for (int mt = 0; mt < 2; mt++)
            #pragma unroll
            for (int nt = 0; nt < 2; nt++)
                #pragma unroll
                for (int r = 0; r < 4; r++) acc[mt][nt][r] = 0.0f;
        #pragma unroll
        for (int ks = 0; ks < 4; ks++) {
            unsigned bb[4];
            ldsm4(bb, Kbuf + kOff + ks * 32);
            #pragma unroll
            for (int mt = 0; mt < 2; mt++) {
                mma16(acc[mt][0], qf[mt][ks], bb[0], bb[2]);
                mma16(acc[mt][1], qf[mt][ks], bb[1], bb[3]);
            }
        }
        #pragma unroll
        for (int mt = 0; mt < 2; mt++)
            #pragma unroll
            for (int nt = 0; nt < 2; nt++) {
                int col = jt * 128 + wid * 16 + nt * 8 + 2 * tg;
                int r1 = g + mt * 16;
                float2 o0; o0.x = acc[mt][nt][0] * scale; o0.y = acc[mt][nt][1] * scale;
                float2 o1; o1.x = acc[mt][nt][2] * scale; o1.y = acc[mt][nt][3] * scale;
                *(float2*)&sS[r1 * SS_LD + col]       = o0;
                *(float2*)&sS[(r1 + 8) * SS_LD + col] = o1;
            }
        __syncthreads();
        if (jt < 6) {
            load_kv(sKVb, Kp, jt + 2, jt & 1, tid);
            asm volatile("cp.async.commit_group;\n");
        }
        if (jt < 7) {
            if (jt < 6) asm volatile("cp.async.wait_group 1;\n");
            else        asm volatile("cp.async.wait_group 0;\n");
            __syncthreads();
        }
    }

    load_kv(sKVb, Vp, 0, 0, tid);
    asm volatile("cp.async.commit_group;\n");

    // ---- phase 2: softmax (warp per row, 4 rows per warp) ----
    {
        for (int rr = 0; rr < 4; rr++) {
            float* srow = &sS[(wid + rr * 8) * SS_LD];
            float m = -1e30f;
            for (int t = lane; t < SEQ; t += 32) m = fmaxf(m, srow[t]);
            #pragma unroll
            for (int o = 16; o; o >>= 1) m = fmaxf(m, __shfl_xor_sync(0xffffffffu, m, o));
            float ssum = 0.0f;
            for (int t = lane; t < SEQ; t += 32) {
                float e = fexp(srow[t] - m);
                srow[t] = e;
                ssum += e;
            }
            #pragma unroll
            for (int o = 16; o; o >>= 1) ssum += __shfl_xor_sync(0xffffffffu, ssum, o);
            float inv = 1.0f / ssum;
            for (int t = lane; t < SEQ; t += 32) srow[t] *= inv;
        }
    }
    __syncthreads();

    // ---- phase 3: write weights f32 + in-place convert P -> fp16 overlay ----
    // Group-wise (8 rows): fp16 writes for group g only clobber float bytes
    // below row 8(g+1) start, all already consumed (see analysis).
    {
        float* Wrow = Wout + ((size_t)(b * NH + h) * SEQ + q0) * SEQ;
        for (int gq = 0; gq < 4; gq++) {
            float4 vv[8];
            #pragma unroll
            for (int i = 0; i < 8; i++) {
                int r = 8 * gq + i;
                vv[i] = *(const float4*)&sS[r * SS_LD + tid * 4];
                *(float4*)(Wrow + (size_t)r * SEQ + tid * 4) = vv[i];
            }
            __syncthreads();
            #pragma unroll
            for (int i = 0; i < 8; i++) {
                int r = 8 * gq + i;
                *(__half2*)(sP + r * SP_LD + tid * 4)     = __floats2half2_rn(vv[i].x, vv[i].y);
                *(__half2*)(sP + r * SP_LD + tid * 4 + 2) = __floats2half2_rn(vv[i].z, vv[i].w);
            }
        }
    }
    __syncthreads();

    load_kv(sKVb, Vp, 1, 1, tid);
    asm volatile("cp.async.commit_group;\n");
    asm volatile("cp.async.wait_group 1;\n");
    __syncthreads();

    // ---- phase 4: ctx = P @ V ----
    float acc2[2][4];
    #pragma unroll
    for (int mt = 0; mt < 2; mt++)
        #pragma unroll
        for (int r = 0; r < 4; r++) acc2[mt][r] = 0.0f;

    for (int kt = 0; kt < 8; kt++) {
        const unsigned Vbuf = sKVb + (unsigned)((kt & 1) * KVBUF_B);
        #pragma unroll
        for (int ks = 0; ks < 8; ks++) {           // 8 x k16 per 128-chunk
            int kcol = kt * 128 + ks * 16;
            unsigned bf[2];
            ldsm2t(bf, Vbuf + vOff + (unsigned)(ks * 16 * KV_LD * 2));
            #pragma unroll
            for (int mt = 0; mt < 2; mt++) {
                unsigned af[4];
                ldsm4(af, sPb + pOff[mt] + (unsigned)(kcol * 2));
                mma16(acc2[mt], af, bf[0], bf[1]);
            }
        }
        __syncthreads();
        if (kt < 6) {
            load_kv(sKVb, Vp, kt + 2, kt & 1, tid);
            asm volatile("cp.async.commit_group;\n");
        }
        if (kt < 7) {
            if (kt < 6) asm volatile("cp.async.wait_group 1;\n");
            else        asm volatile("cp.async.wait_group 0;\n");
            __syncthreads();
        }
    }

    // ctx -> fp16 (feeds wo GEMM)
    #pragma unroll
    for (int mt = 0; mt < 2; mt++)
        #pragma unroll
        for (int half = 0; half < 2; half++) {
            int row = q0 + g + mt * 16 + half * 8;
            int col = h * DH + wid * 8 + 2 * tg;
            *(__half2*)(Ctx + ((size_t)b * SEQ + row) * H + col) =
                __floats2half2_rn(acc2[mt][2 * half], acc2[mt][2 * half + 1]);
        }
}

// ---------------- launch ---------------------------------------------------
extern "C" void kernel_launch(void* const* d_in, const int* in_sizes, int n_in,
                              void* d_out, int out_size)
{
    const float* x   = (const float*)d_in[0];
    const float* wq  = (const float*)d_in[1];
    const float* bq  = (const float*)d_in[2];
    const float* wk  = (const float*)d_in[3];
    const float* bk  = (const float*)d_in[4];
    const float* wv  = (const float*)d_in[5];
    const float* bv  = (const float*)d_in[6];
    const float* wo  = (const float*)d_in[7];
    const float* bo  = (const float*)d_in[8];
    const float* w1  = (const float*)d_in[9];
    const float* b1  = (const float*)d_in[10];
    const float* w2  = (const float*)d_in[11];
    const float* b2  = (const float*)d_in[12];
    const float* g1  = (const float*)d_in[13];
    const float* be1 = (const float*)d_in[14];
    const float* g2  = (const float*)d_in[15];
    const float* be2 = (const float*)d_in[16];

    float* out_x = (float*)d_out;
    float* out_w = (float*)d_out + X_ELEMS;

    __half *px1, *pqkv, *pctx, *px2, *ph, *pwqkvT, *pwoT, *pw1T, *pw2T;
    float *pxres, *pbqkv;
    cudaGetSymbolAddress((void**)&px1,    g_x1h);
    cudaGetSymbolAddress((void**)&pqkv,   g_qkvh);
    cudaGetSymbolAddress((void**)&pctx,   g_ctxh);
    cudaGetSymbolAddress((void**)&pxres,  g_xres);
    cudaGetSymbolAddress((void**)&px2,    g_x2h);
    cudaGetSymbolAddress((void**)&ph,     g_hh);
    cudaGetSymbolAddress((void**)&pwqkvT, g_wqkvT);
    cudaGetSymbolAddress((void**)&pwoT,   g_woT);
    cudaGetSymbolAddress((void**)&pw1T,   g_w1T);
    cudaGetSymbolAddress((void**)&pw2T,   g_w2T);
    cudaGetSymbolAddress((void**)&pbqkv,  g_bqkv);

    cudaFuncSetAttribute(attn_tc,
        cudaFuncAttributeMaxDynamicSharedMemorySize, ATT_SMEM);
    cudaFuncSetAttribute(gemm_tc<0>,
        cudaFuncAttributeMaxDynamicSharedMemorySize, G_SMEM);
    cudaFuncSetAttribute(gemm_tc<1>,
        cudaFuncAttributeMaxDynamicSharedMemorySize, G_SMEM);
    cudaFuncSetAttribute(gemm_tc<2>,
        cudaFuncAttributeMaxDynamicSharedMemorySize, G_SMEM);

    dim3 tb(32, 8);

    // weight prep (fp16 transposed)
    transpose_qkv<<<dim3(H/32, H/32, 3), tb>>>(wq, wk, wv, bq, bk, bv,
                                               pwqkvT, pbqkv);
    transpose_one<<<dim3(H/32, H/32), tb>>>(wo, pwoT, H, H);
    transpose_w12<<<dim3(FF/32, H/32, 2), tb>>>(w1, w2, pw1T, pw2T);

    // LN1 -> fp16
    ln_kernel<<<ROWS, 256>>>(x, g1, be1, px1);

    // fused QKV projection -> fp16
    gemm_tc<1><<<dim3(H3/128, ROWS/128), 256, G_SMEM>>>(
        px1, pwqkvT, pbqkv, nullptr, pqkv, ROWS, H3, H);

    // attention: weights -> d_out (f32), ctx -> fp16
    attn_tc<<<dim3(SEQ/32, NH, BB), 256, ATT_SMEM>>>(pqkv, out_w, pctx);

    // output projection + residual(x) -> f32
    gemm_tc<0><<<dim3(H/128, ROWS/128), 256, G_SMEM>>>(
        pctx, pwoT, bo, x, pxres, ROWS, H, H);

    // LN2 -> fp16
    ln_kernel<<<ROWS, 256>>>(pxres, g2, be2, px2);

    // MLP up + gelu -> fp16
    gemm_tc<2><<<dim3(FF/128, ROWS/128), 256, G_SMEM>>>(
        px2, pw1T, b1, nullptr, ph, ROWS, FF, H);
    // MLP down + residual -> f32 out
    gemm_tc<0><<<dim3(H/128, ROWS/128), 256, G_SMEM>>>(
        ph, pw2T, b2, pxres, out_x, ROWS, H, FF);
}

// round 9
// speedup vs baseline: 5.6447x; 1.0713x over previous
#include <cuda_runtime.h>
#include <cuda_fp16.h>
#include <math.h>

#define H   768
#define NH  12
#define DH  64
#define FF  3072
#define BB  8
#define SEQ 1024
#define ROWS (BB*SEQ)                 // 8192
#define X_ELEMS ((size_t)ROWS*H)      // 6291456
#define H3  (3*H)                     // 2304

// ---------------- scratch (static device allocations) -----------------------
__device__ __half g_x1h [ROWS*H];
__device__ __half g_qkvh[ROWS*H3];
__device__ __half g_ctxh[ROWS*H];
__device__ float  g_xres[ROWS*H];
__device__ __half g_x2h [ROWS*H];
__device__ __half g_hh  [ROWS*FF];
// transposed fp16 weights (W^T: [N][K])
__device__ __half g_wqkvT[H3*H];
__device__ __half g_woT [H*H];
__device__ __half g_w1T [FF*H];
__device__ __half g_w2T [H*FF];
__device__ float  g_bqkv[H3];

// ---------------- helpers ----------------------------------------------------
__device__ __forceinline__ void cp16(unsigned saddr, const void* g) {
    asm volatile("cp.async.cg.shared.global [%0], [%1], 16;\n"
                 :: "r"(saddr), "l"(g));
}

__device__ __forceinline__ void ldsm4(unsigned* r, unsigned saddr) {
    asm volatile("ldmatrix.sync.aligned.m8n8.x4.shared.b16 {%0,%1,%2,%3}, [%4];\n"
                 : "=r"(r[0]), "=r"(r[1]), "=r"(r[2]), "=r"(r[3])
                 : "r"(saddr));
}

__device__ __forceinline__ void ldsm2t(unsigned* r, unsigned saddr) {
    asm volatile("ldmatrix.sync.aligned.m8n8.x2.trans.shared.b16 {%0,%1}, [%2];\n"
                 : "=r"(r[0]), "=r"(r[1])
                 : "r"(saddr));
}

// fp16 mma: D(16x8,f32) += A(16x16,f16) * B(16x8,f16)
__device__ __forceinline__ void mma16(float* d, const unsigned* a,
                                      unsigned b0, unsigned b1) {
    asm volatile(
        "mma.sync.aligned.m16n8k16.row.col.f32.f16.f16.f32 "
        "{%0,%1,%2,%3}, {%4,%5,%6,%7}, {%8,%9}, {%0,%1,%2,%3};\n"
        : "+f"(d[0]), "+f"(d[1]), "+f"(d[2]), "+f"(d[3])
        : "r"(a[0]), "r"(a[1]), "r"(a[2]), "r"(a[3]), "r"(b0), "r"(b1));
}

// ---------------- fast exp (FMA pipe) --------------------------------------
__device__ __forceinline__ float fexp(float x) {
    x = fmaxf(x, -87.0f);
    float t  = x * 1.4426950408889634f;
    float fi = rintf(t);
    float z  = t - fi;
    float p  =            1.535336188319500e-4f;
    p = fmaf(p, z, 1.339887440266574e-3f);
    p = fmaf(p, z, 9.618437357674640e-3f);
    p = fmaf(p, z, 5.550332471162809e-2f);
    p = fmaf(p, z, 2.402264791363012e-1f);
    p = fmaf(p, z, 6.931472028550421e-1f);
    p = fmaf(p, z, 1.0f);
    return __int_as_float(((int)fi + 127) << 23) * p;
}

// ---------------- transpose helpers (f32 [K][N] -> f16 [N][K]) ---------------
__device__ __forceinline__ void tr_tile(const float* __restrict__ s,
                                        __half* __restrict__ d,
                                        int K, int N, int kb, int nb,
                                        float (*t)[33]) {
    #pragma unroll
    for (int i = threadIdx.y; i < 32; i += 8)
        t[i][threadIdx.x] = s[(size_t)(kb + i) * N + nb + threadIdx.x];
    __syncthreads();
    #pragma unroll
    for (int i = threadIdx.y; i < 32; i += 8)
        d[(size_t)(nb + i) * K + kb + threadIdx.x] = __float2half(t[threadIdx.x][i]);
}

__global__ __launch_bounds__(256) void transpose_qkv(
    const float* __restrict__ wq, const float* __restrict__ wk,
    const float* __restrict__ wv,
    const float* __restrict__ bq, const float* __restrict__ bk,
    const float* __restrict__ bv,
    __half* __restrict__ dT, float* __restrict__ bqkv)
{
    __shared__ float t[32][33];
    int z = blockIdx.z;
    const float* s = (z == 0) ? wq : (z == 1) ? wk : wv;
    tr_tile(s, dT + (size_t)z * H * H, H, H, blockIdx.y * 32, blockIdx.x * 32, t);
    if (blockIdx.x == 0 && blockIdx.y == 0) {
        const float* bs = (z == 0) ? bq : (z == 1) ? bk : bv;
        int tid = threadIdx.y * 32 + threadIdx.x;
        for (int i = tid; i < H; i += 256) bqkv[z * H + i] = bs[i];
    }
}

__global__ __launch_bounds__(256) void transpose_one(
    const float* __restrict__ s, __half* __restrict__ d, int K, int N)
{
    __shared__ float t[32][33];
    tr_tile(s, d, K, N, blockIdx.y * 32, blockIdx.x * 32, t);
}

__global__ __launch_bounds__(256) void transpose_w12(
    const float* __restrict__ w1, const float* __restrict__ w2,
    __half* __restrict__ w1T, __half* __restrict__ w2T)
{
    __shared__ float t[32][33];
    if (blockIdx.z == 0)
        tr_tile(w1, w1T, H, FF, blockIdx.y * 32, blockIdx.x * 32, t);
    else
        tr_tile(w2, w2T, FF, H, blockIdx.x * 32, blockIdx.y * 32, t);
}

// ---------------- block reduce -----------------------------------------------
__device__ __forceinline__ float block_sum(float v, float* red) {
    #pragma unroll
    for (int o = 16; o; o >>= 1) v += __shfl_xor_sync(0xffffffffu, v, o);
    int w = threadIdx.x >> 5;
    if ((threadIdx.x & 31) == 0) red[w] = v;
    __syncthreads();
    float t = 0.0f;
    if (threadIdx.x < 32) {
        t = (threadIdx.x < 8) ? red[threadIdx.x] : 0.0f;
        #pragma unroll
        for (int o = 4; o; o >>= 1) t += __shfl_xor_sync(0xffffffffu, t, o);
        if (threadIdx.x == 0) red[0] = t;
    }
    __syncthreads();
    t = red[0];
    __syncthreads();
    return t;
}

// ---------------- layernorm: f32 in -> f16 out -------------------------------
__global__ __launch_bounds__(256) void ln_kernel(
    const float* __restrict__ x, const float* __restrict__ g,
    const float* __restrict__ b, __half* __restrict__ y)
{
    __shared__ float red[8];
    int row = blockIdx.x;
    const float* xr = x + (size_t)row * H;
    int t = threadIdx.x;
    float v0 = xr[t], v1 = xr[t + 256], v2 = xr[t + 512];
    float mu = block_sum(v0 + v1 + v2, red) * (1.0f / H);
    float d0 = v0 - mu, d1 = v1 - mu, d2 = v2 - mu;
    float var = block_sum(d0*d0 + d1*d1 + d2*d2, red) * (1.0f / H);
    float rs = rsqrtf(var + 1e-6f);
    __half* yr = y + (size_t)row * H;
    yr[t]       = __float2half(d0 * rs * g[t]       + b[t]);
    yr[t + 256] = __float2half(d1 * rs * g[t + 256] + b[t + 256]);
    yr[t + 512] = __float2half(d2 * rs * g[t + 512] + b[t + 512]);
}

// ================= FP16 tensor-core GEMM (W transposed [N][K]) ==============
#define ALD 72
#define STAGE_B (128*ALD*2)
#define G_SMEM  (6*STAGE_B)                     // 110592 B

template<int OUT>
__global__ __launch_bounds__(256, 2) void gemm_tc(
    const __half* __restrict__ A, const __half* __restrict__ Wt,
    const float* __restrict__ bias, const float* __restrict__ res,
    void* __restrict__ Cout, int M, int N, int K)
{
    extern __shared__ char smc[];

    const int tid  = threadIdx.x;
    const int wid  = tid >> 5;
    const int lane = tid & 31;
    const int g    = lane >> 2;
    const int tg   = lane & 3;

    const int m0 = blockIdx.y * 128;
    const int n0 = blockIdx.x * 128;
    const int wm = (wid & 3) * 32;
    const int wn = (wid >> 2) * 64;

    unsigned sbase = (unsigned)__cvta_generic_to_shared(smc);

    unsigned aS[4], bS[4];
    const __half* aG[4];
    const __half* bG[4];
    #pragma unroll
    for (int i = 0; i < 4; i++) {
        int c = tid + 256 * i;
        int r = c >> 3, cc = (c & 7) * 8;
        aS[i] = sbase + (unsigned)(r * ALD + cc) * 2;
        aG[i] = A  + (size_t)(m0 + r) * K + cc;
        bS[i] = sbase + 3 * STAGE_B + (unsigned)(r * ALD + cc) * 2;
        bG[i] = Wt + (size_t)(n0 + r) * K + cc;
    }

    const int rsel = (lane >> 3) & 1;
    const int csel = (lane >> 4) & 1;
    unsigned aOff[2], bOff[4];
    #pragma unroll
    for (int mt = 0; mt < 2; mt++)
        aOff[mt] = (unsigned)(((wm + mt * 16 + (lane & 7) + rsel * 8) * ALD
                               + csel * 8) * 2);
    #pragma unroll
    for (int p = 0; p < 4; p++)
        bOff[p] = (unsigned)(((wn + p * 16 + (lane & 7) + rsel * 8) * ALD
                              + csel * 8) * 2);

    float d[2][8][4];
    #pragma unroll
    for (int mt = 0; mt < 2; mt++)
        #pragma unroll
        for (int nt = 0; nt < 8; nt++)
            #pragma unroll
            for (int r = 0; r < 4; r++) d[mt][nt][r] = 0.0f;

    const int KIT = K >> 6;

    auto fill = [&](int it, int st) {
        unsigned so = (unsigned)st * STAGE_B;
        int k0 = it * 64;
        #pragma unroll
        for (int i = 0; i < 4; i++) cp16(aS[i] + so, aG[i] + k0);
        #pragma unroll
        for (int i = 0; i < 4; i++) cp16(bS[i] + so, bG[i] + k0);
    };

    fill(0, 0); asm volatile("cp.async.commit_group;\n");
    fill(1, 1); asm volatile("cp.async.commit_group;\n");

    int st = 0;
    for (int it = 0; it < KIT; it++) {
        asm volatile("cp.async.wait_group 1;\n");
        __syncthreads();
        if (it + 2 < KIT) {
            int s2 = st + 2; if (s2 >= 3) s2 -= 3;
            fill(it + 2, s2);
        }
        asm volatile("cp.async.commit_group;\n");

        const unsigned aStage = sbase + (unsigned)st * STAGE_B;
        const unsigned bStage = sbase + 3 * STAGE_B + (unsigned)st * STAGE_B;
        #pragma unroll
        for (int kk = 0; kk < 4; kk++) {
            unsigned a[2][4], bb[4][4];
            ldsm4(a[0], aStage + aOff[0] + kk * 32);
            ldsm4(a[1], aStage + aOff[1] + kk * 32);
            #pragma unroll
            for (int p = 0; p < 4; p++)
                ldsm4(bb[p], bStage + bOff[p] + kk * 32);
            #pragma unroll
            for (int mt = 0; mt < 2; mt++)
                #pragma unroll
                for (int nt = 0; nt < 8; nt++) {
                    int p = nt >> 1, od = nt & 1;
                    mma16(d[mt][nt], a[mt], bb[p][od], bb[p][od + 2]);
                }
        }
        if (++st >= 3) st = 0;
    }

    #pragma unroll
    for (int mt = 0; mt < 2; mt++) {
        int r0 = m0 + wm + mt * 16 + g;
        #pragma unroll
        for (int nt = 0; nt < 8; nt++) {
            int c = n0 + wn + nt * 8 + 2 * tg;
            float b0 = bias[c], b1 = bias[c + 1];
            #pragma unroll
            for (int half = 0; half < 2; half++) {
                int row = r0 + half * 8;
                size_t base = (size_t)row * N + c;
                float v0 = d[mt][nt][2 * half]     + b0;
                float v1 = d[mt][nt][2 * half + 1] + b1;
                if (OUT == 2) {
                    v0 = 0.5f * v0 * (1.0f + erff(v0 * 0.70710678118654752f));
                    v1 = 0.5f * v1 * (1.0f + erff(v1 * 0.70710678118654752f));
                }
                if (OUT == 0) {
                    v0 += res[base]; v1 += res[base + 1];
                    float2 o; o.x = v0; o.y = v1;
                    *(float2*)((float*)Cout + base) = o;
                } else {
                    *(__half2*)((__half*)Cout + base) = __floats2half2_rn(v0, v1);
                }
            }
        }
    }
}

// ================= fp16 attention, QT=16, 2 CTAs/SM ==========================
// smem: Q 2304 + KV 2x18432 + sS(f32 16x1028) 65792 = 104960 B -> occupancy 2.
#define QT 16
#define KV_LD 72
#define KVBUF_B (128*KV_LD*2)                    // 18432 B
#define SS_LD 1028
#define SP_LD 1032
#define SM_Q   0
#define SM_KV  2304
#define SM_S   (SM_KV + 2*KVBUF_B)               // 39168
#define ATT_SMEM (SM_S + QT*SS_LD*4)             // 104960 B

__device__ __forceinline__ void load_kv(unsigned skv, const __half* gp,
                                        int chunk, int buf, int tid) {
    #pragma unroll
    for (int i = 0; i < 4; i++) {
        int idx = tid + 256 * i;
        int r = idx >> 3, cc = (idx & 7) * 8;
        cp16(skv + (unsigned)(buf * KVBUF_B) + (unsigned)(r * KV_LD + cc) * 2,
             gp + (size_t)(chunk * 128 + r) * H3 + cc);
    }
}

__global__ __launch_bounds__(256, 2) void attn_tc(
    const __half* __restrict__ QKV, float* __restrict__ Wout,
    __half* __restrict__ Ctx)
{
    extern __shared__ char smc[];
    float* sS  = (float*)(smc + SM_S);
    __half* sP = (__half*)(smc + SM_S);    // fp16 overlay after conversion

    const int tid  = threadIdx.x;
    const int wid  = tid >> 5;
    const int lane = tid & 31;
    const int g    = lane >> 2;
    const int tg   = lane & 3;
    const int q0   = blockIdx.x * QT;
    const int h    = blockIdx.y;
    const int b    = blockIdx.z;
    const float scale = 0.03608439182435161f;   // 1/sqrt(768)

    const size_t rowb = (size_t)b * SEQ * H3;
    const __half* Qp = QKV + rowb + (size_t)q0 * H3 + h * DH;
    const __half* Kp = QKV + rowb + H  + h * DH;
    const __half* Vp = QKV + rowb + 2 * H + h * DH;

    unsigned sbase = (unsigned)__cvta_generic_to_shared(smc);
    unsigned sQb  = sbase + SM_Q;
    unsigned sKVb = sbase + SM_KV;
    unsigned sPb  = sbase + SM_S;

    const int rsel = (lane >> 3) & 1;
    const int csel = (lane >> 4) & 1;
    // K-fragment base (rows wid*16..+15 of KV buffer)
    const unsigned kOff =
        (unsigned)(((wid * 16 + (lane & 7) + rsel * 8) * KV_LD + csel * 8) * 2);
    // Q / P fragment bases (rows 0..15)
    const unsigned qOff =
        (unsigned)((((lane & 7) + rsel * 8) * KV_LD + csel * 8) * 2);
    const unsigned pOff =
        (unsigned)((((lane & 7) + rsel * 8) * SP_LD + csel * 8) * 2);
    // V-fragment (trans) base: rows = k, cols = wid*8..+7
    const unsigned vOff = (unsigned)(((lane & 15) * KV_LD + wid * 8) * 2);

    // load Q tile (16 rows x 64 halves = 128 chunks)
    if (tid < 128) {
        int r = tid >> 3, cc = (tid & 7) * 8;
        cp16(sQb + (unsigned)(r * KV_LD + cc) * 2, Qp + (size_t)r * H3 + cc);
    }
    load_kv(sKVb, Kp, 0, 0, tid);
    asm volatile("cp.async.commit_group;\n");
    load_kv(sKVb, Kp, 1, 1, tid);
    asm volatile("cp.async.commit_group;\n");
    asm volatile("cp.async.wait_group 1;\n");
    __syncthreads();

    // Q fragments (4 k16-steps over DH=64)
    unsigned qf[4][4];
    #pragma unroll
    for (int ks = 0; ks < 4; ks++)
        ldsm4(qf[ks], sQb + qOff + ks * 32);

    // ---- phase 1: scores ----
    for (int jt = 0; jt < 8; jt++) {
        const unsigned Kbuf = sKVb + (unsigned)((jt & 1) * KVBUF_B);
        float acc[2][4];
        #pragma unroll
        for (int nt = 0; nt < 2; nt++)
            #pragma unroll
            for (int r = 0; r < 4; r++) acc[nt][r] = 0.0f;
        #pragma unroll
        for (int ks = 0; ks < 4; ks++) {
            unsigned bb[4];
            ldsm4(bb, Kbuf + kOff + ks * 32);
            mma16(acc[0], qf[ks], bb[0], bb[2]);
            mma16(acc[1], qf[ks], bb[1], bb[3]);
        }
        #pragma unroll
        for (int nt = 0; nt < 2; nt++) {
            int col = jt * 128 + wid * 16 + nt * 8 + 2 * tg;
            float2 o0; o0.x = acc[nt][0] * scale; o0.y = acc[nt][1] * scale;
            float2 o1; o1.x = acc[nt][2] * scale; o1.y = acc[nt][3] * scale;
            *(float2*)&sS[g * SS_LD + col]       = o0;
            *(float2*)&sS[(g + 8) * SS_LD + col] = o1;
        }
        __syncthreads();
        if (jt < 6) {
            load_kv(sKVb, Kp, jt + 2, jt & 1, tid);
            asm volatile("cp.async.commit_group;\n");
        }
        if (jt < 7) {
            if (jt < 6) asm volatile("cp.async.wait_group 1;\n");
            else        asm volatile("cp.async.wait_group 0;\n");
            __syncthreads();
        }
    }

    load_kv(sKVb, Vp, 0, 0, tid);
    asm volatile("cp.async.commit_group;\n");

    // ---- phase 2: softmax + fused f32 weights write (2 rows per warp) ----
    {
        for (int rr = 0; rr < 2; rr++) {
            int row = wid + rr * 8;
            float* srow = &sS[row * SS_LD];
            float* Wrow = Wout + ((size_t)(b * NH + h) * SEQ + q0 + row) * SEQ;
            float m = -1e30f;
            for (int t = lane; t < SEQ; t += 32) m = fmaxf(m, srow[t]);
            #pragma unroll
            for (int o = 16; o; o >>= 1) m = fmaxf(m, __shfl_xor_sync(0xffffffffu, m, o));
            float ssum = 0.0f;
            for (int t = lane; t < SEQ; t += 32) {
                float e = fexp(srow[t] - m);
                srow[t] = e;
                ssum += e;
            }
            #pragma unroll
            for (int o = 16; o; o >>= 1) ssum += __shfl_xor_sync(0xffffffffu, ssum, o);
            float inv = 1.0f / ssum;
            for (int t = lane; t < SEQ; t += 32) {
                float p = srow[t] * inv;
                srow[t] = p;
                Wrow[t] = p;
            }
        }
    }
    __syncthreads();

    // ---- phase 3: in-place convert P f32 -> fp16 overlay (2 groups x 8 rows)
    // fp16 rows [8g,8g+8) occupy bytes [g*16512, g*16512+16512) which only
    // overlay f32 rows already consumed in earlier groups.
    for (int gq = 0; gq < 2; gq++) {
        float4 vv[8];
        #pragma unroll
        for (int i = 0; i < 8; i++)
            vv[i] = *(const float4*)&sS[(8 * gq + i) * SS_LD + tid * 4];
        __syncthreads();
        #pragma unroll
        for (int i = 0; i < 8; i++) {
            int r = 8 * gq + i;
            *(__half2*)(sP + r * SP_LD + tid * 4)     = __floats2half2_rn(vv[i].x, vv[i].y);
            *(__half2*)(sP + r * SP_LD + tid * 4 + 2) = __floats2half2_rn(vv[i].z, vv[i].w);
        }
        __syncthreads();
    }

    load_kv(sKVb, Vp, 1, 1, tid);
    asm volatile("cp.async.commit_group;\n");
    asm volatile("cp.async.wait_group 1;\n");
    __syncthreads();

    // ---- phase 4: ctx = P @ V ----
    float acc2[4];
    #pragma unroll
    for (int r = 0; r < 4; r++) acc2[r] = 0.0f;

    for (int kt = 0; kt < 8; kt++) {
        const unsigned Vbuf = sKVb + (unsigned)((kt & 1) * KVBUF_B);
        #pragma unroll
        for (int ks = 0; ks < 8; ks++) {           // 8 x k16 per 128-chunk
            int kcol = kt * 128 + ks * 16;
            unsigned bf[2];
            ldsm2t(bf, Vbuf + vOff + (unsigned)(ks * 16 * KV_LD * 2));
            unsigned af[4];
            ldsm4(af, sPb + pOff + (unsigned)(kcol * 2));
            mma16(acc2, af, bf[0], bf[1]);
        }
        __syncthreads();
        if (kt < 6) {
            load_kv(sKVb, Vp, kt + 2, kt & 1, tid);
            asm volatile("cp.async.commit_group;\n");
        }
        if (kt < 7) {
            if (kt < 6) asm volatile("cp.async.wait_group 1;\n");
            else        asm volatile("cp.async.wait_group 0;\n");
            __syncthreads();
        }
    }

    // ctx -> fp16 (feeds wo GEMM)
    #pragma unroll
    for (int half = 0; half < 2; half++) {
        int row = q0 + g + half * 8;
        int col = h * DH + wid * 8 + 2 * tg;
        *(__half2*)(Ctx + ((size_t)b * SEQ + row) * H + col) =
            __floats2half2_rn(acc2[2 * half], acc2[2 * half + 1]);
    }
}

// ---------------- launch ---------------------------------------------------
extern "C" void kernel_launch(void* const* d_in, const int* in_sizes, int n_in,
                              void* d_out, int out_size)
{
    const float* x   = (const float*)d_in[0];
    const float* wq  = (const float*)d_in[1];
    const float* bq  = (const float*)d_in[2];
    const float* wk  = (const float*)d_in[3];
    const float* bk  = (const float*)d_in[4];
    const float* wv  = (const float*)d_in[5];
    const float* bv  = (const float*)d_in[6];
    const float* wo  = (const float*)d_in[7];
    const float* bo  = (const float*)d_in[8];
    const float* w1  = (const float*)d_in[9];
    const float* b1  = (const float*)d_in[10];
    const float* w2  = (const float*)d_in[11];
    const float* b2  = (const float*)d_in[12];
    const float* g1  = (const float*)d_in[13];
    const float* be1 = (const float*)d_in[14];
    const float* g2  = (const float*)d_in[15];
    const float* be2 = (const float*)d_in[16];

    float* out_x = (float*)d_out;
    float* out_w = (float*)d_out + X_ELEMS;

    __half *px1, *pqkv, *pctx, *px2, *ph, *pwqkvT, *pwoT, *pw1T, *pw2T;
    float *pxres, *pbqkv;
    cudaGetSymbolAddress((void**)&px1,    g_x1h);
    cudaGetSymbolAddress((void**)&pqkv,   g_qkvh);
    cudaGetSymbolAddress((void**)&pctx,   g_ctxh);
    cudaGetSymbolAddress((void**)&pxres,  g_xres);
    cudaGetSymbolAddress((void**)&px2,    g_x2h);
    cudaGetSymbolAddress((void**)&ph,     g_hh);
    cudaGetSymbolAddress((void**)&pwqkvT, g_wqkvT);
    cudaGetSymbolAddress((void**)&pwoT,   g_woT);
    cudaGetSymbolAddress((void**)&pw1T,   g_w1T);
    cudaGetSymbolAddress((void**)&pw2T,   g_w2T);
    cudaGetSymbolAddress((void**)&pbqkv,  g_bqkv);

    cudaFuncSetAttribute(attn_tc,
        cudaFuncAttributeMaxDynamicSharedMemorySize, ATT_SMEM);
    cudaFuncSetAttribute(gemm_tc<0>,
        cudaFuncAttributeMaxDynamicSharedMemorySize, G_SMEM);
    cudaFuncSetAttribute(gemm_tc<1>,
        cudaFuncAttributeMaxDynamicSharedMemorySize, G_SMEM);
    cudaFuncSetAttribute(gemm_tc<2>,
        cudaFuncAttributeMaxDynamicSharedMemorySize, G_SMEM);

    dim3 tb(32, 8);

    // weight prep (fp16 transposed)
    transpose_qkv<<<dim3(H/32, H/32, 3), tb>>>(wq, wk, wv, bq, bk, bv,
                                               pwqkvT, pbqkv);
    transpose_one<<<dim3(H/32, H/32), tb>>>(wo, pwoT, H, H);
    transpose_w12<<<dim3(FF/32, H/32, 2), tb>>>(w1, w2, pw1T, pw2T);

    // LN1 -> fp16
    ln_kernel<<<ROWS, 256>>>(x, g1, be1, px1);

    // fused QKV projection -> fp16
    gemm_tc<1><<<dim3(H3/128, ROWS/128), 256, G_SMEM>>>(
        px1, pwqkvT, pbqkv, nullptr, pqkv, ROWS, H3, H);

    // attention: weights -> d_out (f32), ctx -> fp16
    attn_tc<<<dim3(SEQ/QT, NH, BB), 256, ATT_SMEM>>>(pqkv, out_w, pctx);

    // output projection + residual(x) -> f32
    gemm_tc<0><<<dim3(H/128, ROWS/128), 256, G_SMEM>>>(
        pctx, pwoT, bo, x, pxres, ROWS, H, H);

    // LN2 -> fp16
    ln_kernel<<<ROWS, 256>>>(pxres, g2, be2, px2);

    // MLP up + gelu -> fp16
    gemm_tc<2><<<dim3(FF/128, ROWS/128), 256, G_SMEM>>>(
        px2, pw1T, b1, nullptr, ph, ROWS, FF, H);
    // MLP down + residual -> f32 out
    gemm_tc<0><<<dim3(H/128, ROWS/128), 256, G_SMEM>>>(
        ph, pw2T, b2, pxres, out_x, ROWS, H, FF);
}